// round 1
// baseline (speedup 1.0000x reference)
#include <cuda_runtime.h>
#include <math.h>

#define NN 50000
#define EE 800000

// ---------------- scratch (static __device__, allocation-free) ----------------
__device__ float d_hA[NN * 192];
__device__ float d_hB[NN * 192];
__device__ float d_g[NN * 128];     // [g1(64) | g2(64)] per row
__device__ float d_t[NN * 64];      // intermediate prop(g2)
__device__ int   d_cnt[2][NN];
__device__ int   d_rp[2][NN + 1];
__device__ int   d_cur[2][NN];
__device__ int   d_col[2][EE];
__device__ float d_wgt[2][EE];
__device__ float d_dinv[2][NN];
__device__ int   d_flag[1];         // 1 => edge_index is int64

// graph 0: out-encoder (rows = dst, neighbors = src, degrees over dst)
// graph 1: in-encoder  (rows = src, neighbors = dst, degrees over src)

__global__ void detect_kernel(const int* ei32) {
    __shared__ int any;
    if (threadIdx.x == 0) any = 0;
    __syncthreads();
    if (ei32[2 * threadIdx.x + 1] != 0) atomicExch(&any, 1);
    __syncthreads();
    if (threadIdx.x == 0) d_flag[0] = (any == 0) ? 1 : 0;
}

__global__ void zero_kernel(int n) {
    int i = blockIdx.x * blockDim.x + threadIdx.x;
    if (i < n) { d_cnt[0][i] = 0; d_cnt[1][i] = 0; }
}

__device__ __forceinline__ void load_edge(const void* ei, int e, int t, int& s, int& d) {
    if (d_flag[0]) {
        const long long* p = (const long long*)ei;
        s = (int)p[t]; d = (int)p[e + t];
    } else {
        const int* p = (const int*)ei;
        s = p[t]; d = p[e + t];
    }
}

__global__ void hist_kernel(const void* ei, int e) {
    int t = blockIdx.x * blockDim.x + threadIdx.x;
    if (t >= e) return;
    int s, d;
    load_edge(ei, e, t, s, d);
    atomicAdd(&d_cnt[0][d], 1);
    atomicAdd(&d_cnt[1][s], 1);
}

__global__ void scan_kernel(int which, int n) {
    __shared__ int sums[1024];
    const int* cnt = d_cnt[which];
    int* rp = d_rp[which];
    int tid = threadIdx.x;
    int chunk = (n + 1023) >> 10;
    int start = tid * chunk;
    int stop = min(start + chunk, n);
    int s = 0;
    for (int i = start; i < stop; i++) s += cnt[i];
    sums[tid] = s;
    __syncthreads();
    for (int off = 1; off < 1024; off <<= 1) {
        int v = (tid >= off) ? sums[tid - off] : 0;
        __syncthreads();
        sums[tid] += v;
        __syncthreads();
    }
    int run = (tid == 0) ? 0 : sums[tid - 1];
    for (int i = start; i < stop; i++) { rp[i] = run; run += cnt[i]; }
    if (tid == 1023) rp[n] = sums[1023];
}

__global__ void finalize_kernel(int n) {
    int i = blockIdx.x * blockDim.x + threadIdx.x;
    if (i < n) {
        d_dinv[0][i] = rsqrtf((float)d_cnt[0][i] + 1.0f);
        d_dinv[1][i] = rsqrtf((float)d_cnt[1][i] + 1.0f);
        d_cur[0][i] = d_rp[0][i];
        d_cur[1][i] = d_rp[1][i];
    }
}

__global__ void place_kernel(const void* ei, int e) {
    int t = blockIdx.x * blockDim.x + threadIdx.x;
    if (t >= e) return;
    int s, d;
    load_edge(ei, e, t, s, d);
    float w0 = d_dinv[0][s] * d_dinv[0][d];
    int p0 = atomicAdd(&d_cur[0][d], 1);
    d_col[0][p0] = s; d_wgt[0][p0] = w0;
    float w1 = d_dinv[1][s] * d_dinv[1][d];
    int p1 = atomicAdd(&d_cur[1][s], 1);
    d_col[1][p1] = d; d_wgt[1][p1] = w1;
}

// ---------------- GEMM: Hout[:,0:64]=tanh(H@w0+b0); d_g = H@[w1|w2] ----------
__global__ void __launch_bounds__(256) gemm_kernel(
    const float* __restrict__ H, int din, int n,
    const float* __restrict__ W,    // (3, din, 64)
    const float* __restrict__ b0,   // first 64 biases
    float* __restrict__ hout)       // row stride 192
{
    __shared__ float As[32][65];
    __shared__ float Bs[32][192];
    int tid = threadIdx.x;
    int tm = tid >> 5, tn = tid & 31;
    int row0 = blockIdx.x * 64;
    float acc[8][6];
#pragma unroll
    for (int i = 0; i < 8; i++)
#pragma unroll
        for (int j = 0; j < 6; j++) acc[i][j] = 0.f;

    for (int k0 = 0; k0 < din; k0 += 32) {
#pragma unroll
        for (int i = 0; i < 8; i++) {
            int idx = tid + 256 * i;
            int m = idx >> 5, k = idx & 31;
            int r = row0 + m;
            As[k][m] = (r < n) ? H[r * din + k0 + k] : 0.f;
        }
#pragma unroll
        for (int i = 0; i < 24; i++) {
            int idx = tid + 256 * i;
            int nc = idx % 192, k = idx / 192;
            Bs[k][nc] = W[((nc >> 6) * din + (k0 + k)) * 64 + (nc & 63)];
        }
        __syncthreads();
#pragma unroll
        for (int kk = 0; kk < 32; kk++) {
            float a[8], bb[6];
#pragma unroll
            for (int i = 0; i < 8; i++) a[i] = As[kk][tm * 8 + i];
#pragma unroll
            for (int j = 0; j < 6; j++) bb[j] = Bs[kk][tn + 32 * j];
#pragma unroll
            for (int i = 0; i < 8; i++)
#pragma unroll
                for (int j = 0; j < 6; j++) acc[i][j] = fmaf(a[i], bb[j], acc[i][j]);
        }
        __syncthreads();
    }
#pragma unroll
    for (int i = 0; i < 8; i++) {
        int r = row0 + tm * 8 + i;
        if (r >= n) continue;
#pragma unroll
        for (int j = 0; j < 6; j++) {
            int c = tn + 32 * j;
            float v = acc[i][j];
            if (c < 64) hout[r * 192 + c] = tanhf(v + b0[c]);
            else        d_g[r * 128 + (c - 64)] = v;
        }
    }
}

// ------ fused prop over 128 cols: hout[:,64:128]=tanh(prop(g1)+b1), d_t=prop(g2)
__global__ void prop_fused_kernel(int graph, int n,
                                  float* __restrict__ hout,
                                  const float* __restrict__ b1)
{
    int row = blockIdx.x * 8 + (threadIdx.x >> 5);
    int lane = threadIdx.x & 31;
    if (row >= n) return;
    const int* __restrict__ rp = d_rp[graph];
    const int* __restrict__ colv = d_col[graph];
    const float* __restrict__ wv = d_wgt[graph];
    float di = d_dinv[graph][row];
    float sw = di * di;
    float4 self = reinterpret_cast<const float4*>(d_g + row * 128)[lane];
    float4 acc = make_float4(sw * self.x, sw * self.y, sw * self.z, sw * self.w);
    int beg = rp[row], end = rp[row + 1];
    for (int base = beg; base < end; base += 32) {
        int e = base + lane;
        int jj = 0; float ww = 0.f;
        if (e < end) { jj = colv[e]; ww = wv[e]; }
        int cnt = min(32, end - base);
        for (int u = 0; u < cnt; u++) {
            int j = __shfl_sync(0xffffffffu, jj, u);
            float w = __shfl_sync(0xffffffffu, ww, u);
            float4 v = reinterpret_cast<const float4*>(d_g + j * 128)[lane];
            acc.x = fmaf(w, v.x, acc.x);
            acc.y = fmaf(w, v.y, acc.y);
            acc.z = fmaf(w, v.z, acc.z);
            acc.w = fmaf(w, v.w, acc.w);
        }
    }
    if (lane < 16) {
        int c = lane * 4;
        float4 o;
        o.x = tanhf(acc.x + b1[c + 0]);
        o.y = tanhf(acc.y + b1[c + 1]);
        o.z = tanhf(acc.z + b1[c + 2]);
        o.w = tanhf(acc.w + b1[c + 3]);
        reinterpret_cast<float4*>(hout + row * 192 + 64)[lane] = o;
    } else {
        reinterpret_cast<float4*>(d_t + row * 64)[lane - 16] = acc;
    }
}

// ------ second hop: hout[:,128:192] = tanh(prop(d_t) + b2) -------------------
__global__ void prop64_kernel(int graph, int n,
                              float* __restrict__ hout,
                              const float* __restrict__ b2)
{
    int row = blockIdx.x * 8 + (threadIdx.x >> 5);
    int lane = threadIdx.x & 31;
    if (row >= n) return;
    const int* __restrict__ rp = d_rp[graph];
    const int* __restrict__ colv = d_col[graph];
    const float* __restrict__ wv = d_wgt[graph];
    float di = d_dinv[graph][row];
    float sw = di * di;
    float2 self = reinterpret_cast<const float2*>(d_t + row * 64)[lane];
    float2 acc = make_float2(sw * self.x, sw * self.y);
    int beg = rp[row], end = rp[row + 1];
    for (int base = beg; base < end; base += 32) {
        int e = base + lane;
        int jj = 0; float ww = 0.f;
        if (e < end) { jj = colv[e]; ww = wv[e]; }
        int cnt = min(32, end - base);
        for (int u = 0; u < cnt; u++) {
            int j = __shfl_sync(0xffffffffu, jj, u);
            float w = __shfl_sync(0xffffffffu, ww, u);
            float2 v = reinterpret_cast<const float2*>(d_t + j * 64)[lane];
            acc.x = fmaf(w, v.x, acc.x);
            acc.y = fmaf(w, v.y, acc.y);
        }
    }
    int c = lane * 2;
    float2 o;
    o.x = tanhf(acc.x + b2[c + 0]);
    o.y = tanhf(acc.y + b2[c + 1]);
    reinterpret_cast<float2*>(hout + row * 192 + 128)[lane] = o;
}

extern "C" void kernel_launch(void* const* d_in, const int* in_sizes, int n_in,
                              void* d_out, int out_size)
{
    const float* x = (const float*)d_in[0];
    const void* ei = d_in[1];
    int n = in_sizes[0] / 256;
    int e = in_sizes[1] / 2;
    if (n > NN) n = NN;
    if (e > EE) e = EE;

    detect_kernel<<<1, 256>>>((const int*)ei);
    zero_kernel<<<(n + 255) / 256, 256>>>(n);
    hist_kernel<<<(e + 255) / 256, 256>>>(ei, e);
    scan_kernel<<<1, 1024>>>(0, n);
    scan_kernel<<<1, 1024>>>(1, n);
    finalize_kernel<<<(n + 255) / 256, 256>>>(n);
    place_kernel<<<(e + 255) / 256, 256>>>(ei, e);

    float* hA = nullptr; float* hB = nullptr;
    cudaGetSymbolAddress((void**)&hA, d_hA);
    cudaGetSymbolAddress((void**)&hB, d_hB);

    int gemm_grid = (n + 63) / 64;
    int prop_grid = (n + 7) / 8;

    for (int enc = 0; enc < 2; enc++) {
        const float* w1 = (const float*)d_in[2 + enc * 6 + 0];
        const float* b1 = (const float*)d_in[2 + enc * 6 + 1];
        const float* w2 = (const float*)d_in[2 + enc * 6 + 2];
        const float* b2 = (const float*)d_in[2 + enc * 6 + 3];
        const float* w3 = (const float*)d_in[2 + enc * 6 + 4];
        const float* b3 = (const float*)d_in[2 + enc * 6 + 5];
        float* z = (float*)d_out + (size_t)enc * n * 192;

        // layer 1 (din = 256, input x)
        gemm_kernel<<<gemm_grid, 256>>>(x, 256, n, w1, b1, hA);
        prop_fused_kernel<<<prop_grid, 256>>>(enc, n, hA, b1 + 64);
        prop64_kernel<<<prop_grid, 256>>>(enc, n, hA, b1 + 128);
        // layer 2 (din = 192)
        gemm_kernel<<<gemm_grid, 256>>>(hA, 192, n, w2, b2, hB);
        prop_fused_kernel<<<prop_grid, 256>>>(enc, n, hB, b2 + 64);
        prop64_kernel<<<prop_grid, 256>>>(enc, n, hB, b2 + 128);
        // layer 3 (din = 192) -> output slice
        gemm_kernel<<<gemm_grid, 256>>>(hB, 192, n, w3, b3, z);
        prop_fused_kernel<<<prop_grid, 256>>>(enc, n, z, b3 + 64);
        prop64_kernel<<<prop_grid, 256>>>(enc, n, z, b3 + 128);
    }
}

// round 3
// speedup vs baseline: 2.9247x; 2.9247x over previous
#include <cuda_runtime.h>
#include <cuda_fp16.h>
#include <math.h>
#include <stdint.h>

#define NN 50000
#define EE 800000

// ---------------- scratch (static __device__, allocation-free) ----------------
__device__ __half d_x16[NN * 256];
__device__ __half d_h16A[NN * 192];
__device__ __half d_h16B[NN * 192];
__device__ __half d_g16[NN * 128];   // [g1(64) | g2(64)] per row
__device__ __half d_t16[NN * 64];    // prop(g2)
__device__ __half d_w16[192 * 256];  // current layer weights, [nc][k] K-major
__device__ int   d_cnt[2][NN];
__device__ int   d_rp[2][NN + 1];
__device__ int   d_cur[2][NN];
__device__ int   d_col[2][EE];
__device__ float d_wgt[2][EE];
__device__ float d_dinv[2][NN];
__device__ int   d_bsum[2][512];
__device__ int   d_boff[2][512];
__device__ int   d_flag[1];          // 1 => edge_index is int64

__device__ __forceinline__ uint32_t smem_u32(const void* p) {
    uint32_t a;
    asm("{ .reg .u64 t; cvta.to.shared.u64 t, %1; cvt.u32.u64 %0, t; }" : "=r"(a) : "l"(p));
    return a;
}

// ---------------- graph build ----------------
__global__ void detect_kernel(const int* ei32) {
    __shared__ int any;
    if (threadIdx.x == 0) any = 0;
    __syncthreads();
    if (ei32[2 * threadIdx.x + 1] != 0) atomicExch(&any, 1);
    __syncthreads();
    if (threadIdx.x == 0) d_flag[0] = (any == 0) ? 1 : 0;
}

__global__ void zero_kernel(int n) {
    int i = blockIdx.x * blockDim.x + threadIdx.x;
    if (i < n) { d_cnt[0][i] = 0; d_cnt[1][i] = 0; }
}

__device__ __forceinline__ void load_edge(const void* ei, int e, int t, int& s, int& d) {
    if (d_flag[0]) {
        const long long* p = (const long long*)ei;
        s = (int)p[t]; d = (int)p[e + t];
    } else {
        const int* p = (const int*)ei;
        s = p[t]; d = p[e + t];
    }
}

__global__ void hist_kernel(const void* ei, int e) {
    int t = blockIdx.x * blockDim.x + threadIdx.x;
    if (t >= e) return;
    int s, d;
    load_edge(ei, e, t, s, d);
    atomicAdd(&d_cnt[0][d], 1);
    atomicAdd(&d_cnt[1][s], 1);
}

__global__ void scan1_kernel(int n) {
    int g = blockIdx.y;
    int i = blockIdx.x * 512 + threadIdx.x;
    __shared__ int sh[512];
    sh[threadIdx.x] = (i < n) ? d_cnt[g][i] : 0;
    __syncthreads();
    for (int off = 256; off > 0; off >>= 1) {
        if (threadIdx.x < off) sh[threadIdx.x] += sh[threadIdx.x + off];
        __syncthreads();
    }
    if (threadIdx.x == 0) d_bsum[g][blockIdx.x] = sh[0];
}

__global__ void scan2_kernel(int nchunks, int n) {
    int t = threadIdx.x;
    int g = t >> 9, i = t & 511;
    __shared__ int sh[1024];
    int v = (i < nchunks) ? d_bsum[g][i] : 0;
    int orig = v;
    sh[t] = v;
    __syncthreads();
    for (int off = 1; off < 512; off <<= 1) {
        int add = (i >= off) ? sh[t - off] : 0;
        __syncthreads();
        sh[t] += add;
        __syncthreads();
    }
    d_boff[g][i] = sh[t] - orig;
    if (i == 511) d_rp[g][n] = sh[t];
}

__global__ void scan3_kernel(int n) {
    int g = blockIdx.y;
    int t = threadIdx.x;
    int i = blockIdx.x * 512 + t;
    __shared__ int sh[512];
    int c = (i < n) ? d_cnt[g][i] : 0;
    sh[t] = c;
    __syncthreads();
    for (int off = 1; off < 512; off <<= 1) {
        int add = (t >= off) ? sh[t - off] : 0;
        __syncthreads();
        sh[t] += add;
        __syncthreads();
    }
    if (i < n) {
        int excl = sh[t] - c + d_boff[g][blockIdx.x];
        d_rp[g][i] = excl;
        d_cur[g][i] = excl;
        d_dinv[g][i] = rsqrtf((float)c + 1.0f);
    }
}

__global__ void place_kernel(const void* ei, int e) {
    int t = blockIdx.x * blockDim.x + threadIdx.x;
    if (t >= e) return;
    int s, d;
    load_edge(ei, e, t, s, d);
    float w0 = d_dinv[0][s] * d_dinv[0][d];
    int p0 = atomicAdd(&d_cur[0][d], 1);
    d_col[0][p0] = s; d_wgt[0][p0] = w0;
    float w1 = d_dinv[1][s] * d_dinv[1][d];
    int p1 = atomicAdd(&d_cur[1][s], 1);
    d_col[1][p1] = d; d_wgt[1][p1] = w1;
}

// ---------------- conversions ----------------
__global__ void convx_kernel(const float* __restrict__ x, int n4) {
    int i = blockIdx.x * blockDim.x + threadIdx.x;
    if (i >= n4) return;
    float4 v = reinterpret_cast<const float4*>(x)[i];
    __half2 a = __floats2half2_rn(v.x, v.y);
    __half2 b = __floats2half2_rn(v.z, v.w);
    reinterpret_cast<__half2*>(d_x16)[i * 2] = a;
    reinterpret_cast<__half2*>(d_x16)[i * 2 + 1] = b;
}

__global__ void convw_kernel(const float* __restrict__ W, int din) {
    int idx = blockIdx.x * blockDim.x + threadIdx.x;
    if (idx >= 192 * din) return;
    int r = idx / din, k = idx - r * din;
    d_w16[r * 256 + k] = __float2half(W[((r >> 6) * din + k) * 64 + (r & 63)]);
}

// ---------------- mma.sync GEMM ----------------
// D[128 x 192] = A[128 x din] * B[192 x din]^T  (f16 in, f32 accum)
// cols 0..63 -> tanh(+bias) -> zout / h16out ; cols 64..191 -> d_g16 (fp16)
__global__ void __launch_bounds__(256) gemm_mma_kernel(
    const __half* __restrict__ H, int din, int n,
    const float* __restrict__ bias,
    float* __restrict__ zout, __half* __restrict__ h16out)
{
    extern __shared__ __half smh[];
    const int SA = din + 8;                  // padded row stride (halfs)
    __half* As = smh;                        // [128][SA]
    __half* Bs = smh + 128 * SA;             // [192][SA]
    int tid = threadIdx.x, wid = tid >> 5, lane = tid & 31;
    int row0 = blockIdx.x * 128;
    int dc8 = din >> 3;

    for (int idx = tid; idx < 128 * dc8; idx += 256) {
        int r = idx / dc8, c8 = idx - r * dc8;
        uint4 v = make_uint4(0, 0, 0, 0);
        if (row0 + r < n) v = *reinterpret_cast<const uint4*>(H + (size_t)(row0 + r) * din + c8 * 8);
        *reinterpret_cast<uint4*>(As + r * SA + c8 * 8) = v;
    }
    for (int idx = tid; idx < 192 * dc8; idx += 256) {
        int r = idx / dc8, c8 = idx - r * dc8;
        *reinterpret_cast<uint4*>(Bs + r * SA + c8 * 8) =
            *reinterpret_cast<const uint4*>(d_w16 + r * 256 + c8 * 8);
    }
    __syncthreads();

    float acc[24][4];
#pragma unroll
    for (int i = 0; i < 24; i++)
#pragma unroll
        for (int j = 0; j < 4; j++) acc[i][j] = 0.f;

    int mrow = wid * 16;
    // A ldmatrix.x4 addresses: lanes 0-7 rows 0-7 @k0 | 8-15 rows 8-15 @k0 | 16-23 rows 0-7 @k0+8 | 24-31 rows 8-15 @k0+8
    uint32_t a_base = smem_u32(As + (mrow + (lane & 15)) * SA + (lane >> 4) * 8);
    // B ldmatrix.x2 addresses (lanes 0-15): rows n0+(l&7) @ k0 + ((l>>3)&1)*8
    int lm = lane & 15;
    uint32_t b_base = smem_u32(Bs + (lm & 7) * SA + ((lm >> 3) & 1) * 8);
    uint32_t b_step = 8u * SA * 2u;          // bytes between N-tiles
    int ksteps = din >> 4;

    for (int ks = 0; ks < ksteps; ks++) {
        uint32_t a0, a1, a2, a3;
        asm volatile("ldmatrix.sync.aligned.m8n8.x4.shared.b16 {%0,%1,%2,%3}, [%4];"
            : "=r"(a0), "=r"(a1), "=r"(a2), "=r"(a3) : "r"(a_base + ks * 32));
        uint32_t bb = b_base + ks * 32;
#pragma unroll
        for (int nt = 0; nt < 24; nt++) {
            uint32_t b0r, b1r;
            asm volatile("ldmatrix.sync.aligned.m8n8.x2.shared.b16 {%0,%1}, [%2];"
                : "=r"(b0r), "=r"(b1r) : "r"(bb));
            asm volatile("mma.sync.aligned.m16n8k16.row.col.f32.f16.f16.f32 "
                "{%0,%1,%2,%3}, {%4,%5,%6,%7}, {%8,%9}, {%0,%1,%2,%3};"
                : "+f"(acc[nt][0]), "+f"(acc[nt][1]), "+f"(acc[nt][2]), "+f"(acc[nt][3])
                : "r"(a0), "r"(a1), "r"(a2), "r"(a3), "r"(b0r), "r"(b1r));
            bb += b_step;
        }
    }

    int r0 = row0 + mrow + (lane >> 2);
    int r1 = r0 + 8;
#pragma unroll
    for (int nt = 0; nt < 24; nt++) {
        int c = nt * 8 + (lane & 3) * 2;
        if (c < 64) {
            float vb0 = bias[c], vb1 = bias[c + 1];
            float o00 = tanhf(acc[nt][0] + vb0), o01 = tanhf(acc[nt][1] + vb1);
            float o10 = tanhf(acc[nt][2] + vb0), o11 = tanhf(acc[nt][3] + vb1);
            if (zout) {
                if (r0 < n) *reinterpret_cast<float2*>(zout + (size_t)r0 * 192 + c) = make_float2(o00, o01);
                if (r1 < n) *reinterpret_cast<float2*>(zout + (size_t)r1 * 192 + c) = make_float2(o10, o11);
            }
            if (h16out) {
                if (r0 < n) *reinterpret_cast<__half2*>(h16out + (size_t)r0 * 192 + c) = __floats2half2_rn(o00, o01);
                if (r1 < n) *reinterpret_cast<__half2*>(h16out + (size_t)r1 * 192 + c) = __floats2half2_rn(o10, o11);
            }
        } else {
            int cg = c - 64;
            if (r0 < n) *reinterpret_cast<__half2*>(d_g16 + (size_t)r0 * 128 + cg) = __floats2half2_rn(acc[nt][0], acc[nt][1]);
            if (r1 < n) *reinterpret_cast<__half2*>(d_g16 + (size_t)r1 * 128 + cg) = __floats2half2_rn(acc[nt][2], acc[nt][3]);
        }
    }
}

// ------ fused prop over 128 cols: out[:,64:128]=tanh(prop(g1)+b1), d_t16=prop(g2)
__global__ void prop_fused_kernel(int graph, int n,
                                  float* __restrict__ zout, __half* __restrict__ h16out,
                                  const float* __restrict__ b1)
{
    int row = blockIdx.x * 8 + (threadIdx.x >> 5);
    int lane = threadIdx.x & 31;
    if (row >= n) return;
    const int* __restrict__ rp = d_rp[graph];
    const int* __restrict__ colv = d_col[graph];
    const float* __restrict__ wv = d_wgt[graph];
    float di = d_dinv[graph][row];
    float sw = di * di;
    uint2 su = reinterpret_cast<const uint2*>(d_g16 + (size_t)row * 128)[lane];
    float2 s0 = __half22float2(*reinterpret_cast<__half2*>(&su.x));
    float2 s1 = __half22float2(*reinterpret_cast<__half2*>(&su.y));
    float4 acc = make_float4(sw * s0.x, sw * s0.y, sw * s1.x, sw * s1.y);
    int beg = rp[row], end = rp[row + 1];
    for (int base = beg; base < end; base += 32) {
        int e = base + lane;
        int jj = 0; float ww = 0.f;
        if (e < end) { jj = colv[e]; ww = wv[e]; }
        int cnt = min(32, end - base);
        for (int u = 0; u < cnt; u++) {
            int j = __shfl_sync(0xffffffffu, jj, u);
            float w = __shfl_sync(0xffffffffu, ww, u);
            uint2 vu = reinterpret_cast<const uint2*>(d_g16 + (size_t)j * 128)[lane];
            float2 v0 = __half22float2(*reinterpret_cast<__half2*>(&vu.x));
            float2 v1 = __half22float2(*reinterpret_cast<__half2*>(&vu.y));
            acc.x = fmaf(w, v0.x, acc.x);
            acc.y = fmaf(w, v0.y, acc.y);
            acc.z = fmaf(w, v1.x, acc.z);
            acc.w = fmaf(w, v1.y, acc.w);
        }
    }
    if (lane < 16) {
        int c = lane * 4;
        float4 o;
        o.x = tanhf(acc.x + b1[c + 0]);
        o.y = tanhf(acc.y + b1[c + 1]);
        o.z = tanhf(acc.z + b1[c + 2]);
        o.w = tanhf(acc.w + b1[c + 3]);
        if (zout) reinterpret_cast<float4*>(zout + (size_t)row * 192 + 64)[lane] = o;
        if (h16out) {
            uint2 hu;
            __half2 h0 = __floats2half2_rn(o.x, o.y);
            __half2 h1 = __floats2half2_rn(o.z, o.w);
            hu.x = *reinterpret_cast<uint32_t*>(&h0);
            hu.y = *reinterpret_cast<uint32_t*>(&h1);
            reinterpret_cast<uint2*>(h16out + (size_t)row * 192 + 64)[lane] = hu;
        }
    } else {
        uint2 tu;
        __half2 t0 = __floats2half2_rn(acc.x, acc.y);
        __half2 t1 = __floats2half2_rn(acc.z, acc.w);
        tu.x = *reinterpret_cast<uint32_t*>(&t0);
        tu.y = *reinterpret_cast<uint32_t*>(&t1);
        reinterpret_cast<uint2*>(d_t16 + (size_t)row * 64)[lane - 16] = tu;
    }
}

// ------ second hop: out[:,128:192] = tanh(prop(d_t16) + b2) -------------------
__global__ void prop64_kernel(int graph, int n,
                              float* __restrict__ zout, __half* __restrict__ h16out,
                              const float* __restrict__ b2)
{
    int row = blockIdx.x * 8 + (threadIdx.x >> 5);
    int lane = threadIdx.x & 31;
    if (row >= n) return;
    const int* __restrict__ rp = d_rp[graph];
    const int* __restrict__ colv = d_col[graph];
    const float* __restrict__ wv = d_wgt[graph];
    float di = d_dinv[graph][row];
    float sw = di * di;
    __half2 sh = reinterpret_cast<const __half2*>(d_t16 + (size_t)row * 64)[lane];
    float2 s = __half22float2(sh);
    float2 acc = make_float2(sw * s.x, sw * s.y);
    int beg = rp[row], end = rp[row + 1];
    for (int base = beg; base < end; base += 32) {
        int e = base + lane;
        int jj = 0; float ww = 0.f;
        if (e < end) { jj = colv[e]; ww = wv[e]; }
        int cnt = min(32, end - base);
        for (int u = 0; u < cnt; u++) {
            int j = __shfl_sync(0xffffffffu, jj, u);
            float w = __shfl_sync(0xffffffffu, ww, u);
            __half2 vh = reinterpret_cast<const __half2*>(d_t16 + (size_t)j * 64)[lane];
            float2 v = __half22float2(vh);
            acc.x = fmaf(w, v.x, acc.x);
            acc.y = fmaf(w, v.y, acc.y);
        }
    }
    int c = lane * 2;
    float2 o;
    o.x = tanhf(acc.x + b2[c + 0]);
    o.y = tanhf(acc.y + b2[c + 1]);
    if (zout) reinterpret_cast<float2*>(zout + (size_t)row * 192 + 128)[lane] = o;
    if (h16out) {
        __half2 h = __floats2half2_rn(o.x, o.y);
        reinterpret_cast<__half2*>(h16out + (size_t)row * 192 + 128)[lane] = h;
    }
}

extern "C" void kernel_launch(void* const* d_in, const int* in_sizes, int n_in,
                              void* d_out, int out_size)
{
    const float* x = (const float*)d_in[0];
    const void* ei = d_in[1];
    int n = in_sizes[0] / 256;
    int e = in_sizes[1] / 2;
    if (n > NN) n = NN;
    if (e > EE) e = EE;

    detect_kernel<<<1, 256>>>((const int*)ei);
    zero_kernel<<<(n + 255) / 256, 256>>>(n);
    hist_kernel<<<(e + 255) / 256, 256>>>(ei, e);
    int nchunks = (n + 511) / 512;
    dim3 sgrid(nchunks, 2);
    scan1_kernel<<<sgrid, 512>>>(n);
    scan2_kernel<<<1, 1024>>>(nchunks, n);
    scan3_kernel<<<sgrid, 512>>>(n);
    place_kernel<<<(e + 255) / 256, 256>>>(ei, e);

    convx_kernel<<<(n * 64 + 255) / 256, 256>>>(x, n * 64);

    __half* x16 = nullptr; __half* h16A = nullptr; __half* h16B = nullptr;
    cudaGetSymbolAddress((void**)&x16, d_x16);
    cudaGetSymbolAddress((void**)&h16A, d_h16A);
    cudaGetSymbolAddress((void**)&h16B, d_h16B);

    static int attr_set = 0;
    int smem256 = 320 * (256 + 8) * 2;   // 168960 B
    int smem192 = 320 * (192 + 8) * 2;   // 128000 B
    cudaFuncSetAttribute(gemm_mma_kernel, cudaFuncAttributeMaxDynamicSharedMemorySize, smem256);
    (void)attr_set;

    int gemm_grid = (n + 127) / 128;
    int prop_grid = (n + 7) / 8;

    for (int enc = 0; enc < 2; enc++) {
        const float* w1 = (const float*)d_in[2 + enc * 6 + 0];
        const float* b1 = (const float*)d_in[2 + enc * 6 + 1];
        const float* w2 = (const float*)d_in[2 + enc * 6 + 2];
        const float* b2 = (const float*)d_in[2 + enc * 6 + 3];
        const float* w3 = (const float*)d_in[2 + enc * 6 + 4];
        const float* b3 = (const float*)d_in[2 + enc * 6 + 5];
        float* z = (float*)d_out + (size_t)enc * n * 192;

        // layer 1 (din = 256, input x16) -> h16A
        convw_kernel<<<(192 * 256 + 255) / 256, 256>>>(w1, 256);
        gemm_mma_kernel<<<gemm_grid, 256, smem256>>>(x16, 256, n, b1, nullptr, h16A);
        prop_fused_kernel<<<prop_grid, 256>>>(enc, n, nullptr, h16A, b1 + 64);
        prop64_kernel<<<prop_grid, 256>>>(enc, n, nullptr, h16A, b1 + 128);
        // layer 2 (din = 192) -> h16B
        convw_kernel<<<(192 * 192 + 255) / 256, 256>>>(w2, 192);
        gemm_mma_kernel<<<gemm_grid, 256, smem192>>>(h16A, 192, n, b2, nullptr, h16B);
        prop_fused_kernel<<<prop_grid, 256>>>(enc, n, nullptr, h16B, b2 + 64);
        prop64_kernel<<<prop_grid, 256>>>(enc, n, nullptr, h16B, b2 + 128);
        // layer 3 (din = 192) -> output z (fp32)
        convw_kernel<<<(192 * 192 + 255) / 256, 256>>>(w3, 192);
        gemm_mma_kernel<<<gemm_grid, 256, smem192>>>(h16B, 192, n, b3, z, nullptr);
        prop_fused_kernel<<<prop_grid, 256>>>(enc, n, z, nullptr, b3 + 64);
        prop64_kernel<<<prop_grid, 256>>>(enc, n, z, nullptr, b3 + 128);
    }
}

// round 4
// speedup vs baseline: 3.1008x; 1.0602x over previous
#include <cuda_runtime.h>
#include <cuda_fp16.h>
#include <math.h>
#include <stdint.h>

#define NN 50000
#define EE 800000

// ---------------- scratch (static __device__, allocation-free) ----------------
__device__ __half d_x16[NN * 256];
__device__ __half d_hA[2][NN * 192];
__device__ __half d_hB[2][NN * 192];
__device__ __half d_g16[2][NN * 128];   // [g1(64) | g2(64)] per row
__device__ __half d_t16[2][NN * 64];    // prop(g2)
__device__ __half d_w16all[6][192 * 256]; // [enc*3+layer][nc][k] K-major stride 256
__device__ int   d_cnt[2][NN];
__device__ int   d_rp[2][NN + 1];
__device__ int   d_cur[2][NN];
__device__ int   d_col[2][EE];
__device__ float d_wgt[2][EE];
__device__ float d_dinv[2][NN];
__device__ int   d_bsum[2][512];
__device__ int   d_boff[2][512];
__device__ int   d_flag[1];             // 1 => edge_index is int64

__device__ __forceinline__ uint32_t smem_u32(const void* p) {
    uint32_t a;
    asm("{ .reg .u64 t; cvta.to.shared.u64 t, %1; cvt.u32.u64 %0, t; }" : "=r"(a) : "l"(p));
    return a;
}
__device__ __forceinline__ float tanh_fast(float x) {
    float y;
    asm("tanh.approx.f32 %0, %1;" : "=f"(y) : "f"(x));
    return y;
}

// ---------------- graph build ----------------
__global__ void detect_kernel(const int* ei32) {
    __shared__ int any;
    if (threadIdx.x == 0) any = 0;
    __syncthreads();
    if (ei32[2 * threadIdx.x + 1] != 0) atomicExch(&any, 1);
    __syncthreads();
    if (threadIdx.x == 0) d_flag[0] = (any == 0) ? 1 : 0;
}

__global__ void zero_kernel(int n) {
    int i = blockIdx.x * blockDim.x + threadIdx.x;
    if (i < n) { d_cnt[0][i] = 0; d_cnt[1][i] = 0; }
}

__device__ __forceinline__ void load_edge(const void* ei, int e, int t, int& s, int& d) {
    if (d_flag[0]) {
        const long long* p = (const long long*)ei;
        s = (int)p[t]; d = (int)p[e + t];
    } else {
        const int* p = (const int*)ei;
        s = p[t]; d = p[e + t];
    }
}

__global__ void hist_kernel(const void* ei, int e) {
    int t = blockIdx.x * blockDim.x + threadIdx.x;
    if (t >= e) return;
    int s, d;
    load_edge(ei, e, t, s, d);
    atomicAdd(&d_cnt[0][d], 1);
    atomicAdd(&d_cnt[1][s], 1);
}

__global__ void scan1_kernel(int n) {
    int g = blockIdx.y;
    int i = blockIdx.x * 512 + threadIdx.x;
    __shared__ int sh[512];
    sh[threadIdx.x] = (i < n) ? d_cnt[g][i] : 0;
    __syncthreads();
    for (int off = 256; off > 0; off >>= 1) {
        if (threadIdx.x < off) sh[threadIdx.x] += sh[threadIdx.x + off];
        __syncthreads();
    }
    if (threadIdx.x == 0) d_bsum[g][blockIdx.x] = sh[0];
}

__global__ void scan2_kernel(int nchunks, int n) {
    int t = threadIdx.x;
    int g = t >> 9, i = t & 511;
    __shared__ int sh[1024];
    int v = (i < nchunks) ? d_bsum[g][i] : 0;
    int orig = v;
    sh[t] = v;
    __syncthreads();
    for (int off = 1; off < 512; off <<= 1) {
        int add = (i >= off) ? sh[t - off] : 0;
        __syncthreads();
        sh[t] += add;
        __syncthreads();
    }
    d_boff[g][i] = sh[t] - orig;
    if (i == 511) d_rp[g][n] = sh[t];
}

__global__ void scan3_kernel(int n) {
    int g = blockIdx.y;
    int t = threadIdx.x;
    int i = blockIdx.x * 512 + t;
    __shared__ int sh[512];
    int c = (i < n) ? d_cnt[g][i] : 0;
    sh[t] = c;
    __syncthreads();
    for (int off = 1; off < 512; off <<= 1) {
        int add = (t >= off) ? sh[t - off] : 0;
        __syncthreads();
        sh[t] += add;
        __syncthreads();
    }
    if (i < n) {
        int excl = sh[t] - c + d_boff[g][blockIdx.x];
        d_rp[g][i] = excl;
        d_cur[g][i] = excl;
        d_dinv[g][i] = rsqrtf((float)c + 1.0f);
    }
}

__global__ void place_kernel(const void* ei, int e) {
    int t = blockIdx.x * blockDim.x + threadIdx.x;
    if (t >= e) return;
    int s, d;
    load_edge(ei, e, t, s, d);
    float w0 = d_dinv[0][s] * d_dinv[0][d];
    int p0 = atomicAdd(&d_cur[0][d], 1);
    d_col[0][p0] = s; d_wgt[0][p0] = w0;
    float w1 = d_dinv[1][s] * d_dinv[1][d];
    int p1 = atomicAdd(&d_cur[1][s], 1);
    d_col[1][p1] = d; d_wgt[1][p1] = w1;
}

// ---------------- conversions ----------------
__global__ void convx_kernel(const float* __restrict__ x, int n4) {
    int i = blockIdx.x * blockDim.x + threadIdx.x;
    if (i >= n4) return;
    float4 v = reinterpret_cast<const float4*>(x)[i];
    reinterpret_cast<__half2*>(d_x16)[i * 2] = __floats2half2_rn(v.x, v.y);
    reinterpret_cast<__half2*>(d_x16)[i * 2 + 1] = __floats2half2_rn(v.z, v.w);
}

struct WPtrs { const float* w[6]; };

__global__ void convw_all_kernel(WPtrs wp) {
    int s = blockIdx.y;
    int din = ((s % 3) == 0) ? 256 : 192;
    int idx = blockIdx.x * 256 + threadIdx.x;
    if (idx >= 192 * din) return;
    int r = idx / din, k = idx - r * din;
    d_w16all[s][r * 256 + k] = __float2half(wp.w[s][((r >> 6) * din + k) * 64 + (r & 63)]);
}

// ---------------- mma.sync GEMM (both encoders via blockIdx.y) ----------------
// D[128 x 192] = A[128 x din] * B[192 x din]^T (f16 in, f32 accum)
// cols 0..63 -> tanh(+bias) -> zout / h16out ; cols 64..191 -> d_g16[enc]
__global__ void __launch_bounds__(256) gemm_mma_kernel(
    const __half* __restrict__ H0, const __half* __restrict__ H1,
    int wslot, int din, int n,
    const float* __restrict__ bias0, const float* __restrict__ bias1,
    float* __restrict__ z, __half* __restrict__ h0, __half* __restrict__ h1)
{
    int enc = blockIdx.y;
    const __half* __restrict__ H = enc ? H1 : H0;
    const float* __restrict__ bias = enc ? bias1 : bias0;
    float* zout = z ? z + (size_t)enc * n * 192 : nullptr;
    __half* h16out = enc ? h1 : h0;
    const __half* __restrict__ Wm = d_w16all[enc * 3 + wslot];
    __half* __restrict__ g16 = d_g16[enc];

    extern __shared__ __half smh[];
    const int SA = din + 8;
    __half* As = smh;                 // [128][SA]
    __half* Bs = smh + 128 * SA;      // [192][SA]
    int tid = threadIdx.x, wid = tid >> 5, lane = tid & 31;
    int row0 = blockIdx.x * 128;
    int dc8 = din >> 3;

    for (int idx = tid; idx < 128 * dc8; idx += 256) {
        int r = idx / dc8, c8 = idx - r * dc8;
        uint4 v = make_uint4(0, 0, 0, 0);
        if (row0 + r < n) v = *reinterpret_cast<const uint4*>(H + (size_t)(row0 + r) * din + c8 * 8);
        *reinterpret_cast<uint4*>(As + r * SA + c8 * 8) = v;
    }
    for (int idx = tid; idx < 192 * dc8; idx += 256) {
        int r = idx / dc8, c8 = idx - r * dc8;
        *reinterpret_cast<uint4*>(Bs + r * SA + c8 * 8) =
            *reinterpret_cast<const uint4*>(Wm + r * 256 + c8 * 8);
    }
    __syncthreads();

    float acc[24][4];
#pragma unroll
    for (int i = 0; i < 24; i++)
#pragma unroll
        for (int j = 0; j < 4; j++) acc[i][j] = 0.f;

    int mrow = wid * 16;
    uint32_t a_base = smem_u32(As + (mrow + (lane & 15)) * SA + (lane >> 4) * 8);
    int lm = lane & 15;
    uint32_t b_base = smem_u32(Bs + (lm & 7) * SA + ((lm >> 3) & 1) * 8);
    uint32_t b_step = 8u * SA * 2u;
    int ksteps = din >> 4;

    for (int ks = 0; ks < ksteps; ks++) {
        uint32_t a0, a1, a2, a3;
        asm volatile("ldmatrix.sync.aligned.m8n8.x4.shared.b16 {%0,%1,%2,%3}, [%4];"
            : "=r"(a0), "=r"(a1), "=r"(a2), "=r"(a3) : "r"(a_base + ks * 32));
        uint32_t bb = b_base + ks * 32;
#pragma unroll
        for (int nt = 0; nt < 24; nt++) {
            uint32_t b0r, b1r;
            asm volatile("ldmatrix.sync.aligned.m8n8.x2.shared.b16 {%0,%1}, [%2];"
                : "=r"(b0r), "=r"(b1r) : "r"(bb));
            asm volatile("mma.sync.aligned.m16n8k16.row.col.f32.f16.f16.f32 "
                "{%0,%1,%2,%3}, {%4,%5,%6,%7}, {%8,%9}, {%0,%1,%2,%3};"
                : "+f"(acc[nt][0]), "+f"(acc[nt][1]), "+f"(acc[nt][2]), "+f"(acc[nt][3])
                : "r"(a0), "r"(a1), "r"(a2), "r"(a3), "r"(b0r), "r"(b1r));
            bb += b_step;
        }
    }

    int r0 = row0 + mrow + (lane >> 2);
    int r1 = r0 + 8;
#pragma unroll
    for (int nt = 0; nt < 24; nt++) {
        int c = nt * 8 + (lane & 3) * 2;
        if (c < 64) {
            float vb0 = bias[c], vb1 = bias[c + 1];
            if (zout) {
                float o00 = tanhf(acc[nt][0] + vb0), o01 = tanhf(acc[nt][1] + vb1);
                float o10 = tanhf(acc[nt][2] + vb0), o11 = tanhf(acc[nt][3] + vb1);
                if (r0 < n) *reinterpret_cast<float2*>(zout + (size_t)r0 * 192 + c) = make_float2(o00, o01);
                if (r1 < n) *reinterpret_cast<float2*>(zout + (size_t)r1 * 192 + c) = make_float2(o10, o11);
            } else {
                float o00 = tanh_fast(acc[nt][0] + vb0), o01 = tanh_fast(acc[nt][1] + vb1);
                float o10 = tanh_fast(acc[nt][2] + vb0), o11 = tanh_fast(acc[nt][3] + vb1);
                if (r0 < n) *reinterpret_cast<__half2*>(h16out + (size_t)r0 * 192 + c) = __floats2half2_rn(o00, o01);
                if (r1 < n) *reinterpret_cast<__half2*>(h16out + (size_t)r1 * 192 + c) = __floats2half2_rn(o10, o11);
            }
        } else {
            int cg = c - 64;
            if (r0 < n) *reinterpret_cast<__half2*>(g16 + (size_t)r0 * 128 + cg) = __floats2half2_rn(acc[nt][0], acc[nt][1]);
            if (r1 < n) *reinterpret_cast<__half2*>(g16 + (size_t)r1 * 128 + cg) = __floats2half2_rn(acc[nt][2], acc[nt][3]);
        }
    }
}

// ------ fused prop over 128 cols: out[:,64:128]=tanh(prop(g1)+b1), t16=prop(g2)
__global__ void prop_fused_kernel(int n,
                                  float* __restrict__ z, __half* __restrict__ h0, __half* __restrict__ h1,
                                  const float* __restrict__ b1_0, const float* __restrict__ b1_1)
{
    int enc = blockIdx.y;
    int row = blockIdx.x * 8 + (threadIdx.x >> 5);
    int lane = threadIdx.x & 31;
    if (row >= n) return;
    const __half* __restrict__ g16 = d_g16[enc];
    __half* __restrict__ t16 = d_t16[enc];
    float* zout = z ? z + (size_t)enc * n * 192 : nullptr;
    __half* h16out = enc ? h1 : h0;
    const float* __restrict__ b1 = enc ? b1_1 : b1_0;
    const int* __restrict__ rp = d_rp[enc];
    const int* __restrict__ colv = d_col[enc];
    const float* __restrict__ wv = d_wgt[enc];

    float di = d_dinv[enc][row];
    float sw = di * di;
    uint2 su = reinterpret_cast<const uint2*>(g16 + (size_t)row * 128)[lane];
    float2 s0 = __half22float2(*reinterpret_cast<__half2*>(&su.x));
    float2 s1 = __half22float2(*reinterpret_cast<__half2*>(&su.y));
    float4 acc = make_float4(sw * s0.x, sw * s0.y, sw * s1.x, sw * s1.y);
    int beg = rp[row], end = rp[row + 1];
    for (int base = beg; base < end; base += 32) {
        int e = base + lane;
        int jj = 0; float ww = 0.f;
        if (e < end) { jj = colv[e]; ww = wv[e]; }
        int cnt = min(32, end - base);
        int u = 0;
        for (; u + 4 <= cnt; u += 4) {
            int j0 = __shfl_sync(0xffffffffu, jj, u);
            int j1 = __shfl_sync(0xffffffffu, jj, u + 1);
            int j2 = __shfl_sync(0xffffffffu, jj, u + 2);
            int j3 = __shfl_sync(0xffffffffu, jj, u + 3);
            float w0 = __shfl_sync(0xffffffffu, ww, u);
            float w1 = __shfl_sync(0xffffffffu, ww, u + 1);
            float w2 = __shfl_sync(0xffffffffu, ww, u + 2);
            float w3 = __shfl_sync(0xffffffffu, ww, u + 3);
            uint2 v0 = reinterpret_cast<const uint2*>(g16 + (size_t)j0 * 128)[lane];
            uint2 v1 = reinterpret_cast<const uint2*>(g16 + (size_t)j1 * 128)[lane];
            uint2 v2 = reinterpret_cast<const uint2*>(g16 + (size_t)j2 * 128)[lane];
            uint2 v3 = reinterpret_cast<const uint2*>(g16 + (size_t)j3 * 128)[lane];
            float2 a0 = __half22float2(*reinterpret_cast<__half2*>(&v0.x));
            float2 a1 = __half22float2(*reinterpret_cast<__half2*>(&v0.y));
            acc.x = fmaf(w0, a0.x, acc.x); acc.y = fmaf(w0, a0.y, acc.y);
            acc.z = fmaf(w0, a1.x, acc.z); acc.w = fmaf(w0, a1.y, acc.w);
            a0 = __half22float2(*reinterpret_cast<__half2*>(&v1.x));
            a1 = __half22float2(*reinterpret_cast<__half2*>(&v1.y));
            acc.x = fmaf(w1, a0.x, acc.x); acc.y = fmaf(w1, a0.y, acc.y);
            acc.z = fmaf(w1, a1.x, acc.z); acc.w = fmaf(w1, a1.y, acc.w);
            a0 = __half22float2(*reinterpret_cast<__half2*>(&v2.x));
            a1 = __half22float2(*reinterpret_cast<__half2*>(&v2.y));
            acc.x = fmaf(w2, a0.x, acc.x); acc.y = fmaf(w2, a0.y, acc.y);
            acc.z = fmaf(w2, a1.x, acc.z); acc.w = fmaf(w2, a1.y, acc.w);
            a0 = __half22float2(*reinterpret_cast<__half2*>(&v3.x));
            a1 = __half22float2(*reinterpret_cast<__half2*>(&v3.y));
            acc.x = fmaf(w3, a0.x, acc.x); acc.y = fmaf(w3, a0.y, acc.y);
            acc.z = fmaf(w3, a1.x, acc.z); acc.w = fmaf(w3, a1.y, acc.w);
        }
        for (; u < cnt; u++) {
            int j = __shfl_sync(0xffffffffu, jj, u);
            float w = __shfl_sync(0xffffffffu, ww, u);
            uint2 vu = reinterpret_cast<const uint2*>(g16 + (size_t)j * 128)[lane];
            float2 a0 = __half22float2(*reinterpret_cast<__half2*>(&vu.x));
            float2 a1 = __half22float2(*reinterpret_cast<__half2*>(&vu.y));
            acc.x = fmaf(w, a0.x, acc.x); acc.y = fmaf(w, a0.y, acc.y);
            acc.z = fmaf(w, a1.x, acc.z); acc.w = fmaf(w, a1.y, acc.w);
        }
    }
    if (lane < 16) {
        int c = lane * 4;
        float4 o;
        if (zout) {
            o.x = tanhf(acc.x + b1[c + 0]); o.y = tanhf(acc.y + b1[c + 1]);
            o.z = tanhf(acc.z + b1[c + 2]); o.w = tanhf(acc.w + b1[c + 3]);
            reinterpret_cast<float4*>(zout + (size_t)row * 192 + 64)[lane] = o;
        } else {
            o.x = tanh_fast(acc.x + b1[c + 0]); o.y = tanh_fast(acc.y + b1[c + 1]);
            o.z = tanh_fast(acc.z + b1[c + 2]); o.w = tanh_fast(acc.w + b1[c + 3]);
            uint2 hu;
            __half2 q0 = __floats2half2_rn(o.x, o.y);
            __half2 q1 = __floats2half2_rn(o.z, o.w);
            hu.x = *reinterpret_cast<uint32_t*>(&q0);
            hu.y = *reinterpret_cast<uint32_t*>(&q1);
            reinterpret_cast<uint2*>(h16out + (size_t)row * 192 + 64)[lane] = hu;
        }
    } else {
        uint2 tu;
        __half2 q0 = __floats2half2_rn(acc.x, acc.y);
        __half2 q1 = __floats2half2_rn(acc.z, acc.w);
        tu.x = *reinterpret_cast<uint32_t*>(&q0);
        tu.y = *reinterpret_cast<uint32_t*>(&q1);
        reinterpret_cast<uint2*>(t16 + (size_t)row * 64)[lane - 16] = tu;
    }
}

// ------ second hop: out[:,128:192] = tanh(prop(t16) + b2) -------------------
__global__ void prop64_kernel(int n,
                              float* __restrict__ z, __half* __restrict__ h0, __half* __restrict__ h1,
                              const float* __restrict__ b2_0, const float* __restrict__ b2_1)
{
    int enc = blockIdx.y;
    int row = blockIdx.x * 8 + (threadIdx.x >> 5);
    int lane = threadIdx.x & 31;
    if (row >= n) return;
    const __half* __restrict__ t16 = d_t16[enc];
    float* zout = z ? z + (size_t)enc * n * 192 : nullptr;
    __half* h16out = enc ? h1 : h0;
    const float* __restrict__ b2 = enc ? b2_1 : b2_0;
    const int* __restrict__ rp = d_rp[enc];
    const int* __restrict__ colv = d_col[enc];
    const float* __restrict__ wv = d_wgt[enc];

    float di = d_dinv[enc][row];
    float sw = di * di;
    __half2 sh = reinterpret_cast<const __half2*>(t16 + (size_t)row * 64)[lane];
    float2 s = __half22float2(sh);
    float2 acc = make_float2(sw * s.x, sw * s.y);
    int beg = rp[row], end = rp[row + 1];
    for (int base = beg; base < end; base += 32) {
        int e = base + lane;
        int jj = 0; float ww = 0.f;
        if (e < end) { jj = colv[e]; ww = wv[e]; }
        int cnt = min(32, end - base);
        int u = 0;
        for (; u + 4 <= cnt; u += 4) {
            int j0 = __shfl_sync(0xffffffffu, jj, u);
            int j1 = __shfl_sync(0xffffffffu, jj, u + 1);
            int j2 = __shfl_sync(0xffffffffu, jj, u + 2);
            int j3 = __shfl_sync(0xffffffffu, jj, u + 3);
            float w0 = __shfl_sync(0xffffffffu, ww, u);
            float w1 = __shfl_sync(0xffffffffu, ww, u + 1);
            float w2 = __shfl_sync(0xffffffffu, ww, u + 2);
            float w3 = __shfl_sync(0xffffffffu, ww, u + 3);
            __half2 v0 = reinterpret_cast<const __half2*>(t16 + (size_t)j0 * 64)[lane];
            __half2 v1 = reinterpret_cast<const __half2*>(t16 + (size_t)j1 * 64)[lane];
            __half2 v2 = reinterpret_cast<const __half2*>(t16 + (size_t)j2 * 64)[lane];
            __half2 v3 = reinterpret_cast<const __half2*>(t16 + (size_t)j3 * 64)[lane];
            float2 a;
            a = __half22float2(v0); acc.x = fmaf(w0, a.x, acc.x); acc.y = fmaf(w0, a.y, acc.y);
            a = __half22float2(v1); acc.x = fmaf(w1, a.x, acc.x); acc.y = fmaf(w1, a.y, acc.y);
            a = __half22float2(v2); acc.x = fmaf(w2, a.x, acc.x); acc.y = fmaf(w2, a.y, acc.y);
            a = __half22float2(v3); acc.x = fmaf(w3, a.x, acc.x); acc.y = fmaf(w3, a.y, acc.y);
        }
        for (; u < cnt; u++) {
            int j = __shfl_sync(0xffffffffu, jj, u);
            float w = __shfl_sync(0xffffffffu, ww, u);
            __half2 vh = reinterpret_cast<const __half2*>(t16 + (size_t)j * 64)[lane];
            float2 a = __half22float2(vh);
            acc.x = fmaf(w, a.x, acc.x); acc.y = fmaf(w, a.y, acc.y);
        }
    }
    int c = lane * 2;
    float2 o;
    if (zout) {
        o.x = tanhf(acc.x + b2[c + 0]);
        o.y = tanhf(acc.y + b2[c + 1]);
        reinterpret_cast<float2*>(zout + (size_t)row * 192 + 128)[lane] = o;
    } else {
        o.x = tanh_fast(acc.x + b2[c + 0]);
        o.y = tanh_fast(acc.y + b2[c + 1]);
        reinterpret_cast<__half2*>(h16out + (size_t)row * 192 + 128)[lane] = __floats2half2_rn(o.x, o.y);
    }
}

extern "C" void kernel_launch(void* const* d_in, const int* in_sizes, int n_in,
                              void* d_out, int out_size)
{
    const float* x = (const float*)d_in[0];
    const void* ei = d_in[1];
    int n = in_sizes[0] / 256;
    int e = in_sizes[1] / 2;
    if (n > NN) n = NN;
    if (e > EE) e = EE;

    detect_kernel<<<1, 256>>>((const int*)ei);
    zero_kernel<<<(n + 255) / 256, 256>>>(n);
    hist_kernel<<<(e + 255) / 256, 256>>>(ei, e);
    int nchunks = (n + 511) / 512;
    dim3 sgrid(nchunks, 2);
    scan1_kernel<<<sgrid, 512>>>(n);
    scan2_kernel<<<1, 1024>>>(nchunks, n);
    scan3_kernel<<<sgrid, 512>>>(n);
    place_kernel<<<(e + 255) / 256, 256>>>(ei, e);

    convx_kernel<<<(n * 64 + 255) / 256, 256>>>(x, n * 64);

    WPtrs wp;
    for (int i = 0; i < 6; i++) wp.w[i] = (const float*)d_in[2 + (i / 3) * 6 + (i % 3) * 2];
    convw_all_kernel<<<dim3((192 * 256 + 255) / 256, 6), 256>>>(wp);

    __half* x16 = nullptr; __half* hA0; __half* hA1; __half* hB0; __half* hB1;
    cudaGetSymbolAddress((void**)&x16, d_x16);
    cudaGetSymbolAddress((void**)&hA0, d_hA);
    hA1 = hA0 + (size_t)NN * 192;
    cudaGetSymbolAddress((void**)&hB0, d_hB);
    hB1 = hB0 + (size_t)NN * 192;

    const float* b1_0 = (const float*)d_in[3];
    const float* b2_0 = (const float*)d_in[5];
    const float* b3_0 = (const float*)d_in[7];
    const float* b1_1 = (const float*)d_in[9];
    const float* b2_1 = (const float*)d_in[11];
    const float* b3_1 = (const float*)d_in[13];
    float* z = (float*)d_out;

    int smem256 = 320 * (256 + 8) * 2;
    int smem192 = 320 * (192 + 8) * 2;
    cudaFuncSetAttribute(gemm_mma_kernel, cudaFuncAttributeMaxDynamicSharedMemorySize, smem256);

    dim3 ggrid((n + 127) / 128, 2);
    dim3 pgrid((n + 7) / 8, 2);

    // layer 1 (din=256, input x16 for both encoders) -> hA
    gemm_mma_kernel<<<ggrid, 256, smem256>>>(x16, x16, 0, 256, n, b1_0, b1_1, nullptr, hA0, hA1);
    prop_fused_kernel<<<pgrid, 256>>>(n, nullptr, hA0, hA1, b1_0 + 64, b1_1 + 64);
    prop64_kernel<<<pgrid, 256>>>(n, nullptr, hA0, hA1, b1_0 + 128, b1_1 + 128);
    // layer 2 (din=192) -> hB
    gemm_mma_kernel<<<ggrid, 256, smem192>>>(hA0, hA1, 1, 192, n, b2_0, b2_1, nullptr, hB0, hB1);
    prop_fused_kernel<<<pgrid, 256>>>(n, nullptr, hB0, hB1, b2_0 + 64, b2_1 + 64);
    prop64_kernel<<<pgrid, 256>>>(n, nullptr, hB0, hB1, b2_0 + 128, b2_1 + 128);
    // layer 3 (din=192) -> z (fp32 output)
    gemm_mma_kernel<<<ggrid, 256, smem192>>>(hB0, hB1, 2, 192, n, b3_0, b3_1, z, nullptr, nullptr);
    prop_fused_kernel<<<pgrid, 256>>>(n, z, nullptr, nullptr, b3_0 + 64, b3_1 + 64);
    prop64_kernel<<<pgrid, 256>>>(n, z, nullptr, nullptr, b3_0 + 128, b3_1 + 128);
}

// round 5
// speedup vs baseline: 3.3230x; 1.0717x over previous
#include <cuda_runtime.h>
#include <cuda_fp16.h>
#include <math.h>
#include <stdint.h>

#define NN 50000
#define EE 800000

// ---------------- scratch (static __device__, allocation-free) ----------------
__device__ __half d_x16[NN * 256];
__device__ __half d_hA[2][NN * 192];
__device__ __half d_hB[2][NN * 192];
__device__ __half d_g16[2][NN * 128];   // [g1(64) | g2(64)] per row
__device__ __half d_t16[2][NN * 64];    // prop(g2)
__device__ __half d_w16all[6][192 * 256]; // [enc*3+layer][nc][k] K-major stride 256
__device__ int   d_cnt[2][NN];
__device__ int   d_rp[2][NN + 1];
__device__ int   d_cur[2][NN];
__device__ int   d_col[2][EE];
__device__ float d_wgt[2][EE];
__device__ float d_dinv[2][NN];
__device__ int   d_bsum[2][512];
__device__ int   d_boff[2][512];
__device__ int   d_flag[1];             // 1 => edge_index is int64

__device__ __forceinline__ uint32_t smem_u32(const void* p) {
    uint32_t a;
    asm("{ .reg .u64 t; cvta.to.shared.u64 t, %1; cvt.u32.u64 %0, t; }" : "=r"(a) : "l"(p));
    return a;
}
__device__ __forceinline__ float tanh_fast(float x) {
    float y;
    asm("tanh.approx.f32 %0, %1;" : "=f"(y) : "f"(x));
    return y;
}
__device__ __forceinline__ void cp_async16(uint32_t dst, const void* src, uint32_t src_bytes) {
    asm volatile("cp.async.cg.shared.global [%0], [%1], 16, %2;"
                 :: "r"(dst), "l"(src), "r"(src_bytes) : "memory");
}
#define CP_COMMIT() asm volatile("cp.async.commit_group;" ::: "memory")
#define CP_WAIT(N)  asm volatile("cp.async.wait_group %0;" :: "n"(N) : "memory")

// ---------------- graph build ----------------
__global__ void detect_kernel(const int* ei32) {
    __shared__ int any;
    if (threadIdx.x == 0) any = 0;
    __syncthreads();
    if (ei32[2 * threadIdx.x + 1] != 0) atomicExch(&any, 1);
    __syncthreads();
    if (threadIdx.x == 0) d_flag[0] = (any == 0) ? 1 : 0;
}

__global__ void zero_kernel(int n) {
    int i = blockIdx.x * blockDim.x + threadIdx.x;
    if (i < n) { d_cnt[0][i] = 0; d_cnt[1][i] = 0; }
}

__device__ __forceinline__ void load_edge(const void* ei, int e, int t, int& s, int& d) {
    if (d_flag[0]) {
        const long long* p = (const long long*)ei;
        s = (int)p[t]; d = (int)p[e + t];
    } else {
        const int* p = (const int*)ei;
        s = p[t]; d = p[e + t];
    }
}

__global__ void hist_kernel(const void* ei, int e) {
    int t = blockIdx.x * blockDim.x + threadIdx.x;
    if (t >= e) return;
    int s, d;
    load_edge(ei, e, t, s, d);
    atomicAdd(&d_cnt[0][d], 1);
    atomicAdd(&d_cnt[1][s], 1);
}

__global__ void scan1_kernel(int n) {
    int g = blockIdx.y;
    int i = blockIdx.x * 512 + threadIdx.x;
    __shared__ int sh[512];
    sh[threadIdx.x] = (i < n) ? d_cnt[g][i] : 0;
    __syncthreads();
    for (int off = 256; off > 0; off >>= 1) {
        if (threadIdx.x < off) sh[threadIdx.x] += sh[threadIdx.x + off];
        __syncthreads();
    }
    if (threadIdx.x == 0) d_bsum[g][blockIdx.x] = sh[0];
}

__global__ void scan2_kernel(int nchunks, int n) {
    int t = threadIdx.x;
    int g = t >> 9, i = t & 511;
    __shared__ int sh[1024];
    int v = (i < nchunks) ? d_bsum[g][i] : 0;
    int orig = v;
    sh[t] = v;
    __syncthreads();
    for (int off = 1; off < 512; off <<= 1) {
        int add = (i >= off) ? sh[t - off] : 0;
        __syncthreads();
        sh[t] += add;
        __syncthreads();
    }
    d_boff[g][i] = sh[t] - orig;
    if (i == 511) d_rp[g][n] = sh[t];
}

__global__ void scan3_kernel(int n) {
    int g = blockIdx.y;
    int t = threadIdx.x;
    int i = blockIdx.x * 512 + t;
    __shared__ int sh[512];
    int c = (i < n) ? d_cnt[g][i] : 0;
    sh[t] = c;
    __syncthreads();
    for (int off = 1; off < 512; off <<= 1) {
        int add = (t >= off) ? sh[t - off] : 0;
        __syncthreads();
        sh[t] += add;
        __syncthreads();
    }
    if (i < n) {
        int excl = sh[t] - c + d_boff[g][blockIdx.x];
        d_rp[g][i] = excl;
        d_cur[g][i] = excl;
        d_dinv[g][i] = rsqrtf((float)c + 1.0f);
    }
}

__global__ void place_kernel(const void* ei, int e) {
    int t = blockIdx.x * blockDim.x + threadIdx.x;
    if (t >= e) return;
    int s, d;
    load_edge(ei, e, t, s, d);
    float w0 = d_dinv[0][s] * d_dinv[0][d];
    int p0 = atomicAdd(&d_cur[0][d], 1);
    d_col[0][p0] = s; d_wgt[0][p0] = w0;
    float w1 = d_dinv[1][s] * d_dinv[1][d];
    int p1 = atomicAdd(&d_cur[1][s], 1);
    d_col[1][p1] = d; d_wgt[1][p1] = w1;
}

// ---------------- conversions ----------------
__global__ void convx_kernel(const float* __restrict__ x, int n4) {
    int i = blockIdx.x * blockDim.x + threadIdx.x;
    if (i >= n4) return;
    float4 v = reinterpret_cast<const float4*>(x)[i];
    reinterpret_cast<__half2*>(d_x16)[i * 2] = __floats2half2_rn(v.x, v.y);
    reinterpret_cast<__half2*>(d_x16)[i * 2 + 1] = __floats2half2_rn(v.z, v.w);
}

struct WPtrs { const float* w[6]; };

__global__ void convw_all_kernel(WPtrs wp) {
    int s = blockIdx.y;
    int din = ((s % 3) == 0) ? 256 : 192;
    int idx = blockIdx.x * 256 + threadIdx.x;
    if (idx >= 192 * din) return;
    int r = idx / din, k = idx - r * din;
    d_w16all[s][r * 256 + k] = __float2half(wp.w[s][((r >> 6) * din + k) * 64 + (r & 63)]);
}

// ---------------- mma.sync GEMM, double-buffered cp.async ----------------
// D[128 x 192] = A[128 x din] * B[192 x din]^T (f16 in, f32 accum)
// K pipelined in 64-wide chunks. cols 0..63 -> tanh(+bias); cols 64..191 -> g16.
#define KC 64
#define SKA 72                       // padded chunk row stride (halfs)
#define A_CH (128 * SKA)             // halfs per A chunk buffer
#define B_CH (192 * SKA)
#define BUF_CH (A_CH + B_CH)         // 23040 halfs = 46080 B per buffer

__global__ void __launch_bounds__(256) gemm_mma_kernel(
    const __half* __restrict__ H0, const __half* __restrict__ H1,
    int wslot, int din, int n,
    const float* __restrict__ bias0, const float* __restrict__ bias1,
    float* __restrict__ z, __half* __restrict__ h0, __half* __restrict__ h1)
{
    int enc = blockIdx.y;
    const __half* __restrict__ H = enc ? H1 : H0;
    const float* __restrict__ bias = enc ? bias1 : bias0;
    float* zout = z ? z + (size_t)enc * n * 192 : nullptr;
    __half* h16out = enc ? h1 : h0;
    const __half* __restrict__ Wm = d_w16all[enc * 3 + wslot];
    __half* __restrict__ g16 = d_g16[enc];

    extern __shared__ __half smh[];      // 2 buffers of [A(128xKC) | B(192xKC)]
    int tid = threadIdx.x, wid = tid >> 5, lane = tid & 31;
    int row0 = blockIdx.x * 128;
    int nk = din / KC;

    uint32_t sbase = smem_u32(smh);

    // async load of one 64-wide K chunk into buffer `b`
    auto load_chunk = [&](int b, int kc) {
        uint32_t abuf = sbase + (uint32_t)(b * BUF_CH) * 2u;
        uint32_t bbuf = abuf + (uint32_t)A_CH * 2u;
        int k0 = kc * KC;
        // A: 128 rows x 64 halfs = 1024 x 16B ; 4 per thread
#pragma unroll
        for (int i = 0; i < 4; i++) {
            int idx = tid + 256 * i;            // 0..1023
            int r = idx >> 3, c16 = idx & 7;    // row, 16B unit (8 halfs)
            const __half* src = H + (size_t)(row0 + r) * din + k0 + c16 * 8;
            uint32_t ok = (row0 + r < n) ? 16u : 0u;
            cp_async16(abuf + (uint32_t)(r * SKA + c16 * 8) * 2u, src, ok);
        }
        // B: 192 rows x 64 halfs = 1536 x 16B ; 6 per thread
#pragma unroll
        for (int i = 0; i < 6; i++) {
            int idx = tid + 256 * i;            // 0..1535
            int r = idx >> 3, c16 = idx & 7;
            const __half* src = Wm + (size_t)r * 256 + k0 + c16 * 8;
            cp_async16(bbuf + (uint32_t)(r * SKA + c16 * 8) * 2u, src, 16u);
        }
        CP_COMMIT();
    };

    float acc[24][4];
#pragma unroll
    for (int i = 0; i < 24; i++)
#pragma unroll
        for (int j = 0; j < 4; j++) acc[i][j] = 0.f;

    int mrow = wid * 16;
    uint32_t a_off = (uint32_t)((mrow + (lane & 15)) * SKA + (lane >> 4) * 8) * 2u;
    int lm = lane & 15;
    uint32_t b_off = (uint32_t)(((lm & 7) * SKA) + ((lm >> 3) & 1) * 8) * 2u;
    uint32_t b_step = (uint32_t)(8 * SKA) * 2u;

    load_chunk(0, 0);

    for (int c = 0; c < nk; c++) {
        if (c + 1 < nk) {
            load_chunk((c + 1) & 1, c + 1);
            CP_WAIT(1);
        } else {
            CP_WAIT(0);
        }
        __syncthreads();
        uint32_t abuf = sbase + (uint32_t)((c & 1) * BUF_CH) * 2u;
        uint32_t bbuf = abuf + (uint32_t)A_CH * 2u;
#pragma unroll
        for (int ks = 0; ks < 4; ks++) {
            uint32_t a0, a1, a2, a3;
            asm volatile("ldmatrix.sync.aligned.m8n8.x4.shared.b16 {%0,%1,%2,%3}, [%4];"
                : "=r"(a0), "=r"(a1), "=r"(a2), "=r"(a3) : "r"(abuf + a_off + ks * 32));
            uint32_t bb = bbuf + b_off + ks * 32;
#pragma unroll
            for (int nt = 0; nt < 24; nt++) {
                uint32_t b0r, b1r;
                asm volatile("ldmatrix.sync.aligned.m8n8.x2.shared.b16 {%0,%1}, [%2];"
                    : "=r"(b0r), "=r"(b1r) : "r"(bb));
                asm volatile("mma.sync.aligned.m16n8k16.row.col.f32.f16.f16.f32 "
                    "{%0,%1,%2,%3}, {%4,%5,%6,%7}, {%8,%9}, {%0,%1,%2,%3};"
                    : "+f"(acc[nt][0]), "+f"(acc[nt][1]), "+f"(acc[nt][2]), "+f"(acc[nt][3])
                    : "r"(a0), "r"(a1), "r"(a2), "r"(a3), "r"(b0r), "r"(b1r));
                bb += b_step;
            }
        }
        __syncthreads();
    }

    int r0 = row0 + mrow + (lane >> 2);
    int r1 = r0 + 8;
#pragma unroll
    for (int nt = 0; nt < 24; nt++) {
        int c = nt * 8 + (lane & 3) * 2;
        if (c < 64) {
            float vb0 = bias[c], vb1 = bias[c + 1];
            if (zout) {
                float o00 = tanhf(acc[nt][0] + vb0), o01 = tanhf(acc[nt][1] + vb1);
                float o10 = tanhf(acc[nt][2] + vb0), o11 = tanhf(acc[nt][3] + vb1);
                if (r0 < n) *reinterpret_cast<float2*>(zout + (size_t)r0 * 192 + c) = make_float2(o00, o01);
                if (r1 < n) *reinterpret_cast<float2*>(zout + (size_t)r1 * 192 + c) = make_float2(o10, o11);
            } else {
                float o00 = tanh_fast(acc[nt][0] + vb0), o01 = tanh_fast(acc[nt][1] + vb1);
                float o10 = tanh_fast(acc[nt][2] + vb0), o11 = tanh_fast(acc[nt][3] + vb1);
                if (r0 < n) *reinterpret_cast<__half2*>(h16out + (size_t)r0 * 192 + c) = __floats2half2_rn(o00, o01);
                if (r1 < n) *reinterpret_cast<__half2*>(h16out + (size_t)r1 * 192 + c) = __floats2half2_rn(o10, o11);
            }
        } else {
            int cg = c - 64;
            if (r0 < n) *reinterpret_cast<__half2*>(g16 + (size_t)r0 * 128 + cg) = __floats2half2_rn(acc[nt][0], acc[nt][1]);
            if (r1 < n) *reinterpret_cast<__half2*>(g16 + (size_t)r1 * 128 + cg) = __floats2half2_rn(acc[nt][2], acc[nt][3]);
        }
    }
}

// ------ fused prop over 128 cols: out[:,64:128]=tanh(prop(g1)+b1), t16=prop(g2)
__global__ void prop_fused_kernel(int n,
                                  float* __restrict__ z, __half* __restrict__ h0, __half* __restrict__ h1,
                                  const float* __restrict__ b1_0, const float* __restrict__ b1_1)
{
    int enc = blockIdx.y;
    int row = blockIdx.x * 8 + (threadIdx.x >> 5);
    int lane = threadIdx.x & 31;
    if (row >= n) return;
    const __half* __restrict__ g16 = d_g16[enc];
    __half* __restrict__ t16 = d_t16[enc];
    float* zout = z ? z + (size_t)enc * n * 192 : nullptr;
    __half* h16out = enc ? h1 : h0;
    const float* __restrict__ b1 = enc ? b1_1 : b1_0;
    const int* __restrict__ rp = d_rp[enc];
    const int* __restrict__ colv = d_col[enc];
    const float* __restrict__ wv = d_wgt[enc];

    float di = d_dinv[enc][row];
    float sw = di * di;
    uint2 su = reinterpret_cast<const uint2*>(g16 + (size_t)row * 128)[lane];
    float2 s0 = __half22float2(*reinterpret_cast<__half2*>(&su.x));
    float2 s1 = __half22float2(*reinterpret_cast<__half2*>(&su.y));
    float4 acc = make_float4(sw * s0.x, sw * s0.y, sw * s1.x, sw * s1.y);
    int beg = rp[row], end = rp[row + 1];
    for (int base = beg; base < end; base += 32) {
        int e = base + lane;
        int jj = 0; float ww = 0.f;
        if (e < end) { jj = colv[e]; ww = wv[e]; }
        int cnt = min(32, end - base);
        int u = 0;
        for (; u + 8 <= cnt; u += 8) {
            int j0 = __shfl_sync(0xffffffffu, jj, u);
            int j1 = __shfl_sync(0xffffffffu, jj, u + 1);
            int j2 = __shfl_sync(0xffffffffu, jj, u + 2);
            int j3 = __shfl_sync(0xffffffffu, jj, u + 3);
            int j4 = __shfl_sync(0xffffffffu, jj, u + 4);
            int j5 = __shfl_sync(0xffffffffu, jj, u + 5);
            int j6 = __shfl_sync(0xffffffffu, jj, u + 6);
            int j7 = __shfl_sync(0xffffffffu, jj, u + 7);
            float w0 = __shfl_sync(0xffffffffu, ww, u);
            float w1 = __shfl_sync(0xffffffffu, ww, u + 1);
            float w2 = __shfl_sync(0xffffffffu, ww, u + 2);
            float w3 = __shfl_sync(0xffffffffu, ww, u + 3);
            float w4 = __shfl_sync(0xffffffffu, ww, u + 4);
            float w5 = __shfl_sync(0xffffffffu, ww, u + 5);
            float w6 = __shfl_sync(0xffffffffu, ww, u + 6);
            float w7 = __shfl_sync(0xffffffffu, ww, u + 7);
            uint2 v0 = reinterpret_cast<const uint2*>(g16 + (size_t)j0 * 128)[lane];
            uint2 v1 = reinterpret_cast<const uint2*>(g16 + (size_t)j1 * 128)[lane];
            uint2 v2 = reinterpret_cast<const uint2*>(g16 + (size_t)j2 * 128)[lane];
            uint2 v3 = reinterpret_cast<const uint2*>(g16 + (size_t)j3 * 128)[lane];
            uint2 v4 = reinterpret_cast<const uint2*>(g16 + (size_t)j4 * 128)[lane];
            uint2 v5 = reinterpret_cast<const uint2*>(g16 + (size_t)j5 * 128)[lane];
            uint2 v6 = reinterpret_cast<const uint2*>(g16 + (size_t)j6 * 128)[lane];
            uint2 v7 = reinterpret_cast<const uint2*>(g16 + (size_t)j7 * 128)[lane];
            float2 a0, a1;
#define ACC128(vv, wv_) \
            a0 = __half22float2(*reinterpret_cast<__half2*>(&vv.x)); \
            a1 = __half22float2(*reinterpret_cast<__half2*>(&vv.y)); \
            acc.x = fmaf(wv_, a0.x, acc.x); acc.y = fmaf(wv_, a0.y, acc.y); \
            acc.z = fmaf(wv_, a1.x, acc.z); acc.w = fmaf(wv_, a1.y, acc.w);
            ACC128(v0, w0) ACC128(v1, w1) ACC128(v2, w2) ACC128(v3, w3)
            ACC128(v4, w4) ACC128(v5, w5) ACC128(v6, w6) ACC128(v7, w7)
        }
        for (; u < cnt; u++) {
            int j = __shfl_sync(0xffffffffu, jj, u);
            float w = __shfl_sync(0xffffffffu, ww, u);
            uint2 vu = reinterpret_cast<const uint2*>(g16 + (size_t)j * 128)[lane];
            float2 a0, a1;
            ACC128(vu, w)
#undef ACC128
        }
    }
    if (lane < 16) {
        int c = lane * 4;
        float4 o;
        if (zout) {
            o.x = tanhf(acc.x + b1[c + 0]); o.y = tanhf(acc.y + b1[c + 1]);
            o.z = tanhf(acc.z + b1[c + 2]); o.w = tanhf(acc.w + b1[c + 3]);
            reinterpret_cast<float4*>(zout + (size_t)row * 192 + 64)[lane] = o;
        } else {
            o.x = tanh_fast(acc.x + b1[c + 0]); o.y = tanh_fast(acc.y + b1[c + 1]);
            o.z = tanh_fast(acc.z + b1[c + 2]); o.w = tanh_fast(acc.w + b1[c + 3]);
            uint2 hu;
            __half2 q0 = __floats2half2_rn(o.x, o.y);
            __half2 q1 = __floats2half2_rn(o.z, o.w);
            hu.x = *reinterpret_cast<uint32_t*>(&q0);
            hu.y = *reinterpret_cast<uint32_t*>(&q1);
            reinterpret_cast<uint2*>(h16out + (size_t)row * 192 + 64)[lane] = hu;
        }
    } else {
        uint2 tu;
        __half2 q0 = __floats2half2_rn(acc.x, acc.y);
        __half2 q1 = __floats2half2_rn(acc.z, acc.w);
        tu.x = *reinterpret_cast<uint32_t*>(&q0);
        tu.y = *reinterpret_cast<uint32_t*>(&q1);
        reinterpret_cast<uint2*>(t16 + (size_t)row * 64)[lane - 16] = tu;
    }
}

// ------ second hop: out[:,128:192] = tanh(prop(t16) + b2) -------------------
__global__ void prop64_kernel(int n,
                              float* __restrict__ z, __half* __restrict__ h0, __half* __restrict__ h1,
                              const float* __restrict__ b2_0, const float* __restrict__ b2_1)
{
    int enc = blockIdx.y;
    int row = blockIdx.x * 8 + (threadIdx.x >> 5);
    int lane = threadIdx.x & 31;
    if (row >= n) return;
    const __half* __restrict__ t16 = d_t16[enc];
    float* zout = z ? z + (size_t)enc * n * 192 : nullptr;
    __half* h16out = enc ? h1 : h0;
    const float* __restrict__ b2 = enc ? b2_1 : b2_0;
    const int* __restrict__ rp = d_rp[enc];
    const int* __restrict__ colv = d_col[enc];
    const float* __restrict__ wv = d_wgt[enc];

    float di = d_dinv[enc][row];
    float sw = di * di;
    __half2 sh = reinterpret_cast<const __half2*>(t16 + (size_t)row * 64)[lane];
    float2 s = __half22float2(sh);
    float2 acc = make_float2(sw * s.x, sw * s.y);
    int beg = rp[row], end = rp[row + 1];
    for (int base = beg; base < end; base += 32) {
        int e = base + lane;
        int jj = 0; float ww = 0.f;
        if (e < end) { jj = colv[e]; ww = wv[e]; }
        int cnt = min(32, end - base);
        int u = 0;
        for (; u + 8 <= cnt; u += 8) {
            int j0 = __shfl_sync(0xffffffffu, jj, u);
            int j1 = __shfl_sync(0xffffffffu, jj, u + 1);
            int j2 = __shfl_sync(0xffffffffu, jj, u + 2);
            int j3 = __shfl_sync(0xffffffffu, jj, u + 3);
            int j4 = __shfl_sync(0xffffffffu, jj, u + 4);
            int j5 = __shfl_sync(0xffffffffu, jj, u + 5);
            int j6 = __shfl_sync(0xffffffffu, jj, u + 6);
            int j7 = __shfl_sync(0xffffffffu, jj, u + 7);
            float w0 = __shfl_sync(0xffffffffu, ww, u);
            float w1 = __shfl_sync(0xffffffffu, ww, u + 1);
            float w2 = __shfl_sync(0xffffffffu, ww, u + 2);
            float w3 = __shfl_sync(0xffffffffu, ww, u + 3);
            float w4 = __shfl_sync(0xffffffffu, ww, u + 4);
            float w5 = __shfl_sync(0xffffffffu, ww, u + 5);
            float w6 = __shfl_sync(0xffffffffu, ww, u + 6);
            float w7 = __shfl_sync(0xffffffffu, ww, u + 7);
            __half2 v0 = reinterpret_cast<const __half2*>(t16 + (size_t)j0 * 64)[lane];
            __half2 v1 = reinterpret_cast<const __half2*>(t16 + (size_t)j1 * 64)[lane];
            __half2 v2 = reinterpret_cast<const __half2*>(t16 + (size_t)j2 * 64)[lane];
            __half2 v3 = reinterpret_cast<const __half2*>(t16 + (size_t)j3 * 64)[lane];
            __half2 v4 = reinterpret_cast<const __half2*>(t16 + (size_t)j4 * 64)[lane];
            __half2 v5 = reinterpret_cast<const __half2*>(t16 + (size_t)j5 * 64)[lane];
            __half2 v6 = reinterpret_cast<const __half2*>(t16 + (size_t)j6 * 64)[lane];
            __half2 v7 = reinterpret_cast<const __half2*>(t16 + (size_t)j7 * 64)[lane];
            float2 a;
            a = __half22float2(v0); acc.x = fmaf(w0, a.x, acc.x); acc.y = fmaf(w0, a.y, acc.y);
            a = __half22float2(v1); acc.x = fmaf(w1, a.x, acc.x); acc.y = fmaf(w1, a.y, acc.y);
            a = __half22float2(v2); acc.x = fmaf(w2, a.x, acc.x); acc.y = fmaf(w2, a.y, acc.y);
            a = __half22float2(v3); acc.x = fmaf(w3, a.x, acc.x); acc.y = fmaf(w3, a.y, acc.y);
            a = __half22float2(v4); acc.x = fmaf(w4, a.x, acc.x); acc.y = fmaf(w4, a.y, acc.y);
            a = __half22float2(v5); acc.x = fmaf(w5, a.x, acc.x); acc.y = fmaf(w5, a.y, acc.y);
            a = __half22float2(v6); acc.x = fmaf(w6, a.x, acc.x); acc.y = fmaf(w6, a.y, acc.y);
            a = __half22float2(v7); acc.x = fmaf(w7, a.x, acc.x); acc.y = fmaf(w7, a.y, acc.y);
        }
        for (; u < cnt; u++) {
            int j = __shfl_sync(0xffffffffu, jj, u);
            float w = __shfl_sync(0xffffffffu, ww, u);
            __half2 vh = reinterpret_cast<const __half2*>(t16 + (size_t)j * 64)[lane];
            float2 a = __half22float2(vh);
            acc.x = fmaf(w, a.x, acc.x); acc.y = fmaf(w, a.y, acc.y);
        }
    }
    int c = lane * 2;
    float2 o;
    if (zout) {
        o.x = tanhf(acc.x + b2[c + 0]);
        o.y = tanhf(acc.y + b2[c + 1]);
        reinterpret_cast<float2*>(zout + (size_t)row * 192 + 128)[lane] = o;
    } else {
        o.x = tanh_fast(acc.x + b2[c + 0]);
        o.y = tanh_fast(acc.y + b2[c + 1]);
        reinterpret_cast<__half2*>(h16out + (size_t)row * 192 + 128)[lane] = __floats2half2_rn(o.x, o.y);
    }
}

extern "C" void kernel_launch(void* const* d_in, const int* in_sizes, int n_in,
                              void* d_out, int out_size)
{
    const float* x = (const float*)d_in[0];
    const void* ei = d_in[1];
    int n = in_sizes[0] / 256;
    int e = in_sizes[1] / 2;
    if (n > NN) n = NN;
    if (e > EE) e = EE;

    detect_kernel<<<1, 256>>>((const int*)ei);
    zero_kernel<<<(n + 255) / 256, 256>>>(n);
    hist_kernel<<<(e + 255) / 256, 256>>>(ei, e);
    int nchunks = (n + 511) / 512;
    dim3 sgrid(nchunks, 2);
    scan1_kernel<<<sgrid, 512>>>(n);
    scan2_kernel<<<1, 1024>>>(nchunks, n);
    scan3_kernel<<<sgrid, 512>>>(n);
    place_kernel<<<(e + 255) / 256, 256>>>(ei, e);

    convx_kernel<<<(n * 64 + 255) / 256, 256>>>(x, n * 64);

    WPtrs wp;
    for (int i = 0; i < 6; i++) wp.w[i] = (const float*)d_in[2 + (i / 3) * 6 + (i % 3) * 2];
    convw_all_kernel<<<dim3((192 * 256 + 255) / 256, 6), 256>>>(wp);

    __half* x16 = nullptr; __half* hA0; __half* hA1; __half* hB0; __half* hB1;
    cudaGetSymbolAddress((void**)&x16, d_x16);
    cudaGetSymbolAddress((void**)&hA0, d_hA);
    hA1 = hA0 + (size_t)NN * 192;
    cudaGetSymbolAddress((void**)&hB0, d_hB);
    hB1 = hB0 + (size_t)NN * 192;

    const float* b1_0 = (const float*)d_in[3];
    const float* b2_0 = (const float*)d_in[5];
    const float* b3_0 = (const float*)d_in[7];
    const float* b1_1 = (const float*)d_in[9];
    const float* b2_1 = (const float*)d_in[11];
    const float* b3_1 = (const float*)d_in[13];
    float* z = (float*)d_out;

    int smem_gemm = 2 * BUF_CH * 2;   // 92160 B
    cudaFuncSetAttribute(gemm_mma_kernel, cudaFuncAttributeMaxDynamicSharedMemorySize, smem_gemm);

    dim3 ggrid((n + 127) / 128, 2);
    dim3 pgrid((n + 7) / 8, 2);

    // layer 1 (din=256, input x16 for both encoders) -> hA
    gemm_mma_kernel<<<ggrid, 256, smem_gemm>>>(x16, x16, 0, 256, n, b1_0, b1_1, nullptr, hA0, hA1);
    prop_fused_kernel<<<pgrid, 256>>>(n, nullptr, hA0, hA1, b1_0 + 64, b1_1 + 64);
    prop64_kernel<<<pgrid, 256>>>(n, nullptr, hA0, hA1, b1_0 + 128, b1_1 + 128);
    // layer 2 (din=192) -> hB
    gemm_mma_kernel<<<ggrid, 256, smem_gemm>>>(hA0, hA1, 1, 192, n, b2_0, b2_1, nullptr, hB0, hB1);
    prop_fused_kernel<<<pgrid, 256>>>(n, nullptr, hB0, hB1, b2_0 + 64, b2_1 + 64);
    prop64_kernel<<<pgrid, 256>>>(n, nullptr, hB0, hB1, b2_0 + 128, b2_1 + 128);
    // layer 3 (din=192) -> z (fp32 output)
    gemm_mma_kernel<<<ggrid, 256, smem_gemm>>>(hB0, hB1, 2, 192, n, b3_0, b3_1, z, nullptr, nullptr);
    prop_fused_kernel<<<pgrid, 256>>>(n, z, nullptr, nullptr, b3_0 + 64, b3_1 + 64);
    prop64_kernel<<<pgrid, 256>>>(n, z, nullptr, nullptr, b3_0 + 128, b3_1 + 128);
}

// round 6
// speedup vs baseline: 3.4516x; 1.0387x over previous
#include <cuda_runtime.h>
#include <cuda_fp16.h>
#include <math.h>
#include <stdint.h>

#define NN 50000
#define EE 800000

// ---------------- scratch (static __device__, allocation-free) ----------------
__device__ __half d_x16[NN * 256];
__device__ __half d_hA[2][NN * 192];
__device__ __half d_hB[2][NN * 192];
__device__ __half d_g16[2][NN * 128];   // [g1(64) | g2(64)] per row
__device__ __half d_t16[2][NN * 64];    // prop(g2)
__device__ __half d_w16all[6][192 * 256]; // [enc*3+layer][nc][k] K-major stride 256
__device__ int   d_cnt[2][NN];
__device__ int   d_rp[2][NN + 1];
__device__ int   d_cur[2][NN];
__device__ int   d_col[2][EE];
__device__ float d_wgt[2][EE];
__device__ float d_dinv[2][NN];
__device__ int   d_bsum[2][512];
__device__ int   d_boff[2][512];
__device__ int   d_flag[1];             // 1 => edge_index is int64

__device__ __forceinline__ uint32_t smem_u32(const void* p) {
    uint32_t a;
    asm("{ .reg .u64 t; cvta.to.shared.u64 t, %1; cvt.u32.u64 %0, t; }" : "=r"(a) : "l"(p));
    return a;
}
__device__ __forceinline__ float tanh_fast(float x) {
    float y;
    asm("tanh.approx.f32 %0, %1;" : "=f"(y) : "f"(x));
    return y;
}
__device__ __forceinline__ void cp_async16(uint32_t dst, const void* src, uint32_t src_bytes) {
    asm volatile("cp.async.cg.shared.global [%0], [%1], 16, %2;"
                 :: "r"(dst), "l"(src), "r"(src_bytes) : "memory");
}
#define CP_COMMIT() asm volatile("cp.async.commit_group;" ::: "memory")
#define CP_WAIT(N)  asm volatile("cp.async.wait_group %0;" :: "n"(N) : "memory")

// ---------------- graph build ----------------
// zero + dtype detect merged (block 0 does detect)
__global__ void zero_detect_kernel(const int* ei32, int n) {
    int i = blockIdx.x * blockDim.x + threadIdx.x;
    if (i < n) { d_cnt[0][i] = 0; d_cnt[1][i] = 0; }
    if (blockIdx.x == 0) {
        __shared__ int any;
        if (threadIdx.x == 0) any = 0;
        __syncthreads();
        if (ei32[2 * threadIdx.x + 1] != 0) atomicExch(&any, 1);
        __syncthreads();
        if (threadIdx.x == 0) d_flag[0] = (any == 0) ? 1 : 0;
    }
}

__device__ __forceinline__ void load_edge(const void* ei, int e, int t, int& s, int& d) {
    if (d_flag[0]) {
        const long long* p = (const long long*)ei;
        s = (int)p[t]; d = (int)p[e + t];
    } else {
        const int* p = (const int*)ei;
        s = p[t]; d = p[e + t];
    }
}

__global__ void hist_kernel(const void* ei, int e) {
    int t = blockIdx.x * blockDim.x + threadIdx.x;
    if (t >= e) return;
    int s, d;
    load_edge(ei, e, t, s, d);
    atomicAdd(&d_cnt[0][d], 1);
    atomicAdd(&d_cnt[1][s], 1);
}

__global__ void scan1_kernel(int n) {
    int g = blockIdx.y;
    int i = blockIdx.x * 512 + threadIdx.x;
    __shared__ int sh[512];
    sh[threadIdx.x] = (i < n) ? d_cnt[g][i] : 0;
    __syncthreads();
    for (int off = 256; off > 0; off >>= 1) {
        if (threadIdx.x < off) sh[threadIdx.x] += sh[threadIdx.x + off];
        __syncthreads();
    }
    if (threadIdx.x == 0) d_bsum[g][blockIdx.x] = sh[0];
}

__global__ void scan2_kernel(int nchunks, int n) {
    int t = threadIdx.x;
    int g = t >> 9, i = t & 511;
    __shared__ int sh[1024];
    int v = (i < nchunks) ? d_bsum[g][i] : 0;
    int orig = v;
    sh[t] = v;
    __syncthreads();
    for (int off = 1; off < 512; off <<= 1) {
        int add = (i >= off) ? sh[t - off] : 0;
        __syncthreads();
        sh[t] += add;
        __syncthreads();
    }
    d_boff[g][i] = sh[t] - orig;
    if (i == 511) d_rp[g][n] = sh[t];
}

__global__ void scan3_kernel(int n) {
    int g = blockIdx.y;
    int t = threadIdx.x;
    int i = blockIdx.x * 512 + t;
    __shared__ int sh[512];
    int c = (i < n) ? d_cnt[g][i] : 0;
    sh[t] = c;
    __syncthreads();
    for (int off = 1; off < 512; off <<= 1) {
        int add = (t >= off) ? sh[t - off] : 0;
        __syncthreads();
        sh[t] += add;
        __syncthreads();
    }
    if (i < n) {
        int excl = sh[t] - c + d_boff[g][blockIdx.x];
        d_rp[g][i] = excl;
        d_cur[g][i] = excl;
        d_dinv[g][i] = rsqrtf((float)c + 1.0f);
    }
}

__global__ void place_kernel(const void* ei, int e) {
    int t = blockIdx.x * blockDim.x + threadIdx.x;
    if (t >= e) return;
    int s, d;
    load_edge(ei, e, t, s, d);
    float w0 = d_dinv[0][s] * d_dinv[0][d];
    int p0 = atomicAdd(&d_cur[0][d], 1);
    d_col[0][p0] = s; d_wgt[0][p0] = w0;
    float w1 = d_dinv[1][s] * d_dinv[1][d];
    int p1 = atomicAdd(&d_cur[1][s], 1);
    d_col[1][p1] = d; d_wgt[1][p1] = w1;
}

// ---------------- conversions ----------------
__global__ void convx_kernel(const float* __restrict__ x, int n4) {
    int i = blockIdx.x * blockDim.x + threadIdx.x;
    if (i >= n4) return;
    float4 v = reinterpret_cast<const float4*>(x)[i];
    reinterpret_cast<__half2*>(d_x16)[i * 2] = __floats2half2_rn(v.x, v.y);
    reinterpret_cast<__half2*>(d_x16)[i * 2 + 1] = __floats2half2_rn(v.z, v.w);
}

struct WPtrs { const float* w[6]; };

__global__ void convw_all_kernel(WPtrs wp) {
    int s = blockIdx.y;
    int din = ((s % 3) == 0) ? 256 : 192;
    int idx = blockIdx.x * 256 + threadIdx.x;
    if (idx >= 192 * din) return;
    int r = idx / din, k = idx - r * din;
    d_w16all[s][r * 256 + k] = __float2half(wp.w[s][((r >> 6) * din + k) * 64 + (r & 63)]);
}

// ---------------- mma.sync GEMM, double-buffered cp.async ----------------
#define KC 64
#define SKA 72
#define A_CH (128 * SKA)
#define B_CH (192 * SKA)
#define BUF_CH (A_CH + B_CH)

__global__ void __launch_bounds__(256) gemm_mma_kernel(
    const __half* __restrict__ H0, const __half* __restrict__ H1,
    int wslot, int din, int n,
    const float* __restrict__ bias0, const float* __restrict__ bias1,
    float* __restrict__ z, __half* __restrict__ h0, __half* __restrict__ h1)
{
    int enc = blockIdx.y;
    const __half* __restrict__ H = enc ? H1 : H0;
    const float* __restrict__ bias = enc ? bias1 : bias0;
    float* zout = z ? z + (size_t)enc * n * 192 : nullptr;
    __half* h16out = enc ? h1 : h0;
    const __half* __restrict__ Wm = d_w16all[enc * 3 + wslot];
    __half* __restrict__ g16 = d_g16[enc];

    extern __shared__ __half smh[];
    int tid = threadIdx.x, wid = tid >> 5, lane = tid & 31;
    int row0 = blockIdx.x * 128;
    int nk = din / KC;

    uint32_t sbase = smem_u32(smh);

    auto load_chunk = [&](int b, int kc) {
        uint32_t abuf = sbase + (uint32_t)(b * BUF_CH) * 2u;
        uint32_t bbuf = abuf + (uint32_t)A_CH * 2u;
        int k0 = kc * KC;
#pragma unroll
        for (int i = 0; i < 4; i++) {
            int idx = tid + 256 * i;
            int r = idx >> 3, c16 = idx & 7;
            const __half* src = H + (size_t)(row0 + r) * din + k0 + c16 * 8;
            uint32_t ok = (row0 + r < n) ? 16u : 0u;
            cp_async16(abuf + (uint32_t)(r * SKA + c16 * 8) * 2u, src, ok);
        }
#pragma unroll
        for (int i = 0; i < 6; i++) {
            int idx = tid + 256 * i;
            int r = idx >> 3, c16 = idx & 7;
            const __half* src = Wm + (size_t)r * 256 + k0 + c16 * 8;
            cp_async16(bbuf + (uint32_t)(r * SKA + c16 * 8) * 2u, src, 16u);
        }
        CP_COMMIT();
    };

    float acc[24][4];
#pragma unroll
    for (int i = 0; i < 24; i++)
#pragma unroll
        for (int j = 0; j < 4; j++) acc[i][j] = 0.f;

    int mrow = wid * 16;
    uint32_t a_off = (uint32_t)((mrow + (lane & 15)) * SKA + (lane >> 4) * 8) * 2u;
    // B ldmatrix.x4: lane groups 0-7/8-15/16-23/24-31 -> (nt,k0),(nt,k0+8),(nt+1,k0),(nt+1,k0+8)
    uint32_t b_off = (uint32_t)((((lane >> 4) * 8 + (lane & 7)) * SKA) + ((lane >> 3) & 1) * 8) * 2u;
    uint32_t b_step2 = (uint32_t)(16 * SKA) * 2u;   // 2 N-tiles

    load_chunk(0, 0);

    for (int c = 0; c < nk; c++) {
        if (c + 1 < nk) {
            load_chunk((c + 1) & 1, c + 1);
            CP_WAIT(1);
        } else {
            CP_WAIT(0);
        }
        __syncthreads();
        uint32_t abuf = sbase + (uint32_t)((c & 1) * BUF_CH) * 2u;
        uint32_t bbuf = abuf + (uint32_t)A_CH * 2u;
#pragma unroll
        for (int ks = 0; ks < 4; ks++) {
            uint32_t a0, a1, a2, a3;
            asm volatile("ldmatrix.sync.aligned.m8n8.x4.shared.b16 {%0,%1,%2,%3}, [%4];"
                : "=r"(a0), "=r"(a1), "=r"(a2), "=r"(a3) : "r"(abuf + a_off + ks * 32));
            uint32_t bb = bbuf + b_off + ks * 32;
#pragma unroll
            for (int nt2 = 0; nt2 < 12; nt2++) {
                uint32_t b0r, b1r, b2r, b3r;
                asm volatile("ldmatrix.sync.aligned.m8n8.x4.shared.b16 {%0,%1,%2,%3}, [%4];"
                    : "=r"(b0r), "=r"(b1r), "=r"(b2r), "=r"(b3r) : "r"(bb));
                asm volatile("mma.sync.aligned.m16n8k16.row.col.f32.f16.f16.f32 "
                    "{%0,%1,%2,%3}, {%4,%5,%6,%7}, {%8,%9}, {%0,%1,%2,%3};"
                    : "+f"(acc[2*nt2][0]), "+f"(acc[2*nt2][1]), "+f"(acc[2*nt2][2]), "+f"(acc[2*nt2][3])
                    : "r"(a0), "r"(a1), "r"(a2), "r"(a3), "r"(b0r), "r"(b1r));
                asm volatile("mma.sync.aligned.m16n8k16.row.col.f32.f16.f16.f32 "
                    "{%0,%1,%2,%3}, {%4,%5,%6,%7}, {%8,%9}, {%0,%1,%2,%3};"
                    : "+f"(acc[2*nt2+1][0]), "+f"(acc[2*nt2+1][1]), "+f"(acc[2*nt2+1][2]), "+f"(acc[2*nt2+1][3])
                    : "r"(a0), "r"(a1), "r"(a2), "r"(a3), "r"(b2r), "r"(b3r));
                bb += b_step2;
            }
        }
        __syncthreads();
    }

    int r0 = row0 + mrow + (lane >> 2);
    int r1 = r0 + 8;
#pragma unroll
    for (int nt = 0; nt < 24; nt++) {
        int c = nt * 8 + (lane & 3) * 2;
        if (c < 64) {
            float vb0 = bias[c], vb1 = bias[c + 1];
            if (zout) {
                float o00 = tanhf(acc[nt][0] + vb0), o01 = tanhf(acc[nt][1] + vb1);
                float o10 = tanhf(acc[nt][2] + vb0), o11 = tanhf(acc[nt][3] + vb1);
                if (r0 < n) *reinterpret_cast<float2*>(zout + (size_t)r0 * 192 + c) = make_float2(o00, o01);
                if (r1 < n) *reinterpret_cast<float2*>(zout + (size_t)r1 * 192 + c) = make_float2(o10, o11);
            } else {
                float o00 = tanh_fast(acc[nt][0] + vb0), o01 = tanh_fast(acc[nt][1] + vb1);
                float o10 = tanh_fast(acc[nt][2] + vb0), o11 = tanh_fast(acc[nt][3] + vb1);
                if (r0 < n) *reinterpret_cast<__half2*>(h16out + (size_t)r0 * 192 + c) = __floats2half2_rn(o00, o01);
                if (r1 < n) *reinterpret_cast<__half2*>(h16out + (size_t)r1 * 192 + c) = __floats2half2_rn(o10, o11);
            }
        } else {
            int cg = c - 64;
            if (r0 < n) *reinterpret_cast<__half2*>(g16 + (size_t)r0 * 128 + cg) = __floats2half2_rn(acc[nt][0], acc[nt][1]);
            if (r1 < n) *reinterpret_cast<__half2*>(g16 + (size_t)r1 * 128 + cg) = __floats2half2_rn(acc[nt][2], acc[nt][3]);
        }
    }
}

// ------ fused prop over 128 cols ------
__global__ void prop_fused_kernel(int n,
                                  float* __restrict__ z, __half* __restrict__ h0, __half* __restrict__ h1,
                                  const float* __restrict__ b1_0, const float* __restrict__ b1_1)
{
    int enc = blockIdx.y;
    int row = blockIdx.x * 8 + (threadIdx.x >> 5);
    int lane = threadIdx.x & 31;
    if (row >= n) return;
    const __half* __restrict__ g16 = d_g16[enc];
    __half* __restrict__ t16 = d_t16[enc];
    float* zout = z ? z + (size_t)enc * n * 192 : nullptr;
    __half* h16out = enc ? h1 : h0;
    const float* __restrict__ b1 = enc ? b1_1 : b1_0;
    const int* __restrict__ rp = d_rp[enc];
    const int* __restrict__ colv = d_col[enc];
    const float* __restrict__ wv = d_wgt[enc];

    float di = d_dinv[enc][row];
    float sw = di * di;
    uint2 su = reinterpret_cast<const uint2*>(g16 + (size_t)row * 128)[lane];
    float2 s0 = __half22float2(*reinterpret_cast<__half2*>(&su.x));
    float2 s1 = __half22float2(*reinterpret_cast<__half2*>(&su.y));
    float4 acc = make_float4(sw * s0.x, sw * s0.y, sw * s1.x, sw * s1.y);
    int beg = rp[row], end = rp[row + 1];
    for (int base = beg; base < end; base += 32) {
        int e = base + lane;
        int jj = 0; float ww = 0.f;
        if (e < end) { jj = colv[e]; ww = wv[e]; }
        int cnt = min(32, end - base);
        int u = 0;
        for (; u + 8 <= cnt; u += 8) {
            int j0 = __shfl_sync(0xffffffffu, jj, u);
            int j1 = __shfl_sync(0xffffffffu, jj, u + 1);
            int j2 = __shfl_sync(0xffffffffu, jj, u + 2);
            int j3 = __shfl_sync(0xffffffffu, jj, u + 3);
            int j4 = __shfl_sync(0xffffffffu, jj, u + 4);
            int j5 = __shfl_sync(0xffffffffu, jj, u + 5);
            int j6 = __shfl_sync(0xffffffffu, jj, u + 6);
            int j7 = __shfl_sync(0xffffffffu, jj, u + 7);
            float w0 = __shfl_sync(0xffffffffu, ww, u);
            float w1 = __shfl_sync(0xffffffffu, ww, u + 1);
            float w2 = __shfl_sync(0xffffffffu, ww, u + 2);
            float w3 = __shfl_sync(0xffffffffu, ww, u + 3);
            float w4 = __shfl_sync(0xffffffffu, ww, u + 4);
            float w5 = __shfl_sync(0xffffffffu, ww, u + 5);
            float w6 = __shfl_sync(0xffffffffu, ww, u + 6);
            float w7 = __shfl_sync(0xffffffffu, ww, u + 7);
            uint2 v0 = reinterpret_cast<const uint2*>(g16 + (size_t)j0 * 128)[lane];
            uint2 v1 = reinterpret_cast<const uint2*>(g16 + (size_t)j1 * 128)[lane];
            uint2 v2 = reinterpret_cast<const uint2*>(g16 + (size_t)j2 * 128)[lane];
            uint2 v3 = reinterpret_cast<const uint2*>(g16 + (size_t)j3 * 128)[lane];
            uint2 v4 = reinterpret_cast<const uint2*>(g16 + (size_t)j4 * 128)[lane];
            uint2 v5 = reinterpret_cast<const uint2*>(g16 + (size_t)j5 * 128)[lane];
            uint2 v6 = reinterpret_cast<const uint2*>(g16 + (size_t)j6 * 128)[lane];
            uint2 v7 = reinterpret_cast<const uint2*>(g16 + (size_t)j7 * 128)[lane];
            float2 a0, a1;
#define ACC128(vv, wv_) \
            a0 = __half22float2(*reinterpret_cast<__half2*>(&vv.x)); \
            a1 = __half22float2(*reinterpret_cast<__half2*>(&vv.y)); \
            acc.x = fmaf(wv_, a0.x, acc.x); acc.y = fmaf(wv_, a0.y, acc.y); \
            acc.z = fmaf(wv_, a1.x, acc.z); acc.w = fmaf(wv_, a1.y, acc.w);
            ACC128(v0, w0) ACC128(v1, w1) ACC128(v2, w2) ACC128(v3, w3)
            ACC128(v4, w4) ACC128(v5, w5) ACC128(v6, w6) ACC128(v7, w7)
        }
        for (; u < cnt; u++) {
            int j = __shfl_sync(0xffffffffu, jj, u);
            float w = __shfl_sync(0xffffffffu, ww, u);
            uint2 vu = reinterpret_cast<const uint2*>(g16 + (size_t)j * 128)[lane];
            float2 a0, a1;
            ACC128(vu, w)
#undef ACC128
        }
    }
    if (lane < 16) {
        int c = lane * 4;
        float4 o;
        if (zout) {
            o.x = tanhf(acc.x + b1[c + 0]); o.y = tanhf(acc.y + b1[c + 1]);
            o.z = tanhf(acc.z + b1[c + 2]); o.w = tanhf(acc.w + b1[c + 3]);
            reinterpret_cast<float4*>(zout + (size_t)row * 192 + 64)[lane] = o;
        } else {
            o.x = tanh_fast(acc.x + b1[c + 0]); o.y = tanh_fast(acc.y + b1[c + 1]);
            o.z = tanh_fast(acc.z + b1[c + 2]); o.w = tanh_fast(acc.w + b1[c + 3]);
            uint2 hu;
            __half2 q0 = __floats2half2_rn(o.x, o.y);
            __half2 q1 = __floats2half2_rn(o.z, o.w);
            hu.x = *reinterpret_cast<uint32_t*>(&q0);
            hu.y = *reinterpret_cast<uint32_t*>(&q1);
            reinterpret_cast<uint2*>(h16out + (size_t)row * 192 + 64)[lane] = hu;
        }
    } else {
        uint2 tu;
        __half2 q0 = __floats2half2_rn(acc.x, acc.y);
        __half2 q1 = __floats2half2_rn(acc.z, acc.w);
        tu.x = *reinterpret_cast<uint32_t*>(&q0);
        tu.y = *reinterpret_cast<uint32_t*>(&q1);
        reinterpret_cast<uint2*>(t16 + (size_t)row * 64)[lane - 16] = tu;
    }
}

// ------ second hop ------
__global__ void prop64_kernel(int n,
                              float* __restrict__ z, __half* __restrict__ h0, __half* __restrict__ h1,
                              const float* __restrict__ b2_0, const float* __restrict__ b2_1)
{
    int enc = blockIdx.y;
    int row = blockIdx.x * 8 + (threadIdx.x >> 5);
    int lane = threadIdx.x & 31;
    if (row >= n) return;
    const __half* __restrict__ t16 = d_t16[enc];
    float* zout = z ? z + (size_t)enc * n * 192 : nullptr;
    __half* h16out = enc ? h1 : h0;
    const float* __restrict__ b2 = enc ? b2_1 : b2_0;
    const int* __restrict__ rp = d_rp[enc];
    const int* __restrict__ colv = d_col[enc];
    const float* __restrict__ wv = d_wgt[enc];

    float di = d_dinv[enc][row];
    float sw = di * di;
    __half2 sh = reinterpret_cast<const __half2*>(t16 + (size_t)row * 64)[lane];
    float2 s = __half22float2(sh);
    float2 acc = make_float2(sw * s.x, sw * s.y);
    int beg = rp[row], end = rp[row + 1];
    for (int base = beg; base < end; base += 32) {
        int e = base + lane;
        int jj = 0; float ww = 0.f;
        if (e < end) { jj = colv[e]; ww = wv[e]; }
        int cnt = min(32, end - base);
        int u = 0;
        for (; u + 8 <= cnt; u += 8) {
            int j0 = __shfl_sync(0xffffffffu, jj, u);
            int j1 = __shfl_sync(0xffffffffu, jj, u + 1);
            int j2 = __shfl_sync(0xffffffffu, jj, u + 2);
            int j3 = __shfl_sync(0xffffffffu, jj, u + 3);
            int j4 = __shfl_sync(0xffffffffu, jj, u + 4);
            int j5 = __shfl_sync(0xffffffffu, jj, u + 5);
            int j6 = __shfl_sync(0xffffffffu, jj, u + 6);
            int j7 = __shfl_sync(0xffffffffu, jj, u + 7);
            float w0 = __shfl_sync(0xffffffffu, ww, u);
            float w1 = __shfl_sync(0xffffffffu, ww, u + 1);
            float w2 = __shfl_sync(0xffffffffu, ww, u + 2);
            float w3 = __shfl_sync(0xffffffffu, ww, u + 3);
            float w4 = __shfl_sync(0xffffffffu, ww, u + 4);
            float w5 = __shfl_sync(0xffffffffu, ww, u + 5);
            float w6 = __shfl_sync(0xffffffffu, ww, u + 6);
            float w7 = __shfl_sync(0xffffffffu, ww, u + 7);
            __half2 v0 = reinterpret_cast<const __half2*>(t16 + (size_t)j0 * 64)[lane];
            __half2 v1 = reinterpret_cast<const __half2*>(t16 + (size_t)j1 * 64)[lane];
            __half2 v2 = reinterpret_cast<const __half2*>(t16 + (size_t)j2 * 64)[lane];
            __half2 v3 = reinterpret_cast<const __half2*>(t16 + (size_t)j3 * 64)[lane];
            __half2 v4 = reinterpret_cast<const __half2*>(t16 + (size_t)j4 * 64)[lane];
            __half2 v5 = reinterpret_cast<const __half2*>(t16 + (size_t)j5 * 64)[lane];
            __half2 v6 = reinterpret_cast<const __half2*>(t16 + (size_t)j6 * 64)[lane];
            __half2 v7 = reinterpret_cast<const __half2*>(t16 + (size_t)j7 * 64)[lane];
            float2 a;
            a = __half22float2(v0); acc.x = fmaf(w0, a.x, acc.x); acc.y = fmaf(w0, a.y, acc.y);
            a = __half22float2(v1); acc.x = fmaf(w1, a.x, acc.x); acc.y = fmaf(w1, a.y, acc.y);
            a = __half22float2(v2); acc.x = fmaf(w2, a.x, acc.x); acc.y = fmaf(w2, a.y, acc.y);
            a = __half22float2(v3); acc.x = fmaf(w3, a.x, acc.x); acc.y = fmaf(w3, a.y, acc.y);
            a = __half22float2(v4); acc.x = fmaf(w4, a.x, acc.x); acc.y = fmaf(w4, a.y, acc.y);
            a = __half22float2(v5); acc.x = fmaf(w5, a.x, acc.x); acc.y = fmaf(w5, a.y, acc.y);
            a = __half22float2(v6); acc.x = fmaf(w6, a.x, acc.x); acc.y = fmaf(w6, a.y, acc.y);
            a = __half22float2(v7); acc.x = fmaf(w7, a.x, acc.x); acc.y = fmaf(w7, a.y, acc.y);
        }
        for (; u < cnt; u++) {
            int j = __shfl_sync(0xffffffffu, jj, u);
            float w = __shfl_sync(0xffffffffu, ww, u);
            __half2 vh = reinterpret_cast<const __half2*>(t16 + (size_t)j * 64)[lane];
            float2 a = __half22float2(vh);
            acc.x = fmaf(w, a.x, acc.x); acc.y = fmaf(w, a.y, acc.y);
        }
    }
    int c = lane * 2;
    float2 o;
    if (zout) {
        o.x = tanhf(acc.x + b2[c + 0]);
        o.y = tanhf(acc.y + b2[c + 1]);
        reinterpret_cast<float2*>(zout + (size_t)row * 192 + 128)[lane] = o;
    } else {
        o.x = tanh_fast(acc.x + b2[c + 0]);
        o.y = tanh_fast(acc.y + b2[c + 1]);
        reinterpret_cast<__half2*>(h16out + (size_t)row * 192 + 128)[lane] = __floats2half2_rn(o.x, o.y);
    }
}

extern "C" void kernel_launch(void* const* d_in, const int* in_sizes, int n_in,
                              void* d_out, int out_size)
{
    const float* x = (const float*)d_in[0];
    const void* ei = d_in[1];
    int n = in_sizes[0] / 256;
    int e = in_sizes[1] / 2;
    if (n > NN) n = NN;
    if (e > EE) e = EE;

    // one-time side stream + events (created on first call, before capture)
    static cudaStream_t s2 = nullptr;
    static cudaEvent_t evFork = nullptr, evJoin = nullptr;
    if (s2 == nullptr) {
        cudaStreamCreateWithFlags(&s2, cudaStreamNonBlocking);
        cudaEventCreateWithFlags(&evFork, cudaEventDisableTiming);
        cudaEventCreateWithFlags(&evJoin, cudaEventDisableTiming);
    }

    __half* x16 = nullptr; __half* hA0; __half* hA1; __half* hB0; __half* hB1;
    cudaGetSymbolAddress((void**)&x16, d_x16);
    cudaGetSymbolAddress((void**)&hA0, d_hA);
    hA1 = hA0 + (size_t)NN * 192;
    cudaGetSymbolAddress((void**)&hB0, d_hB);
    hB1 = hB0 + (size_t)NN * 192;

    const float* b1_0 = (const float*)d_in[3];
    const float* b2_0 = (const float*)d_in[5];
    const float* b3_0 = (const float*)d_in[7];
    const float* b1_1 = (const float*)d_in[9];
    const float* b2_1 = (const float*)d_in[11];
    const float* b3_1 = (const float*)d_in[13];
    float* z = (float*)d_out;

    int smem_gemm = 2 * BUF_CH * 2;
    cudaFuncSetAttribute(gemm_mma_kernel, cudaFuncAttributeMaxDynamicSharedMemorySize, smem_gemm);

    dim3 ggrid((n + 127) / 128, 2);
    dim3 pgrid((n + 7) / 8, 2);

    WPtrs wp;
    for (int i = 0; i < 6; i++) wp.w[i] = (const float*)d_in[2 + (i / 3) * 6 + (i % 3) * 2];

    // ---- fork: side stream does conversions + layer-1 GEMM (graph-independent)
    cudaEventRecord(evFork, 0);
    cudaStreamWaitEvent(s2, evFork, 0);
    convx_kernel<<<(n * 64 + 255) / 256, 256, 0, s2>>>(x, n * 64);
    convw_all_kernel<<<dim3((192 * 256 + 255) / 256, 6), 256, 0, s2>>>(wp);
    gemm_mma_kernel<<<ggrid, 256, smem_gemm, s2>>>(x16, x16, 0, 256, n, b1_0, b1_1, nullptr, hA0, hA1);
    cudaEventRecord(evJoin, s2);

    // ---- main stream: graph build chain
    zero_detect_kernel<<<(n + 255) / 256, 256>>>((const int*)ei, n);
    hist_kernel<<<(e + 255) / 256, 256>>>(ei, e);
    int nchunks = (n + 511) / 512;
    dim3 sgrid(nchunks, 2);
    scan1_kernel<<<sgrid, 512>>>(n);
    scan2_kernel<<<1, 1024>>>(nchunks, n);
    scan3_kernel<<<sgrid, 512>>>(n);
    place_kernel<<<(e + 255) / 256, 256>>>(ei, e);

    // ---- join: props need both the graph and the layer-1 GEMM output
    cudaStreamWaitEvent(0, evJoin, 0);

    prop_fused_kernel<<<pgrid, 256>>>(n, nullptr, hA0, hA1, b1_0 + 64, b1_1 + 64);
    prop64_kernel<<<pgrid, 256>>>(n, nullptr, hA0, hA1, b1_0 + 128, b1_1 + 128);
    // layer 2
    gemm_mma_kernel<<<ggrid, 256, smem_gemm>>>(hA0, hA1, 1, 192, n, b2_0, b2_1, nullptr, hB0, hB1);
    prop_fused_kernel<<<pgrid, 256>>>(n, nullptr, hB0, hB1, b2_0 + 64, b2_1 + 64);
    prop64_kernel<<<pgrid, 256>>>(n, nullptr, hB0, hB1, b2_0 + 128, b2_1 + 128);
    // layer 3 -> z (fp32 output)
    gemm_mma_kernel<<<ggrid, 256, smem_gemm>>>(hB0, hB1, 2, 192, n, b3_0, b3_1, z, nullptr, nullptr);
    prop_fused_kernel<<<pgrid, 256>>>(n, z, nullptr, nullptr, b3_0 + 64, b3_1 + 64);
    prop64_kernel<<<pgrid, 256>>>(n, z, nullptr, nullptr, b3_0 + 128, b3_1 + 128);
}